// round 12
// baseline (speedup 1.0000x reference)
#include <cuda_runtime.h>
#include <cuda_fp16.h>
#include <math.h>

// Problem constants
#define Tc   128
#define Bc   1024
#define LAGc 6
#define Hc   256
#define H4c  1024
#define TBc  (Tc * Bc)      // 131072
#define BHc  (Bc * Hc)      // 262144

// Persistent recurrence kernel geometry (fp16, K-chunk 32)
#define NGRP   8
#define NSUB   16
#define NBLK   (NGRP * NSUB)
#define W0STRH 264          // smem row stride (halves) layer0 weights (K=256)
#define W1STRH 520          // layer1 (K=512)
#define AHSTR  40           // A staging row stride (halves): 80B, conflict-free
#define ABUFH  (128 * AHSTR)  // halves per A buffer (5120)
#define SMEM_P ((64 * W0STRH + 64 * W1STRH + 3 * ABUFH) * 2)   // 131072 bytes

// fp16 GEMM pipeline: 3 stages x (A 128x32 + B 128x32) halves, stride 40
#define ASTGH  (128 * AHSTR)          // 5120 halves per operand
#define GSTGH  (2 * ASTGH)            // 10240 halves per stage
#define SMEM_GH (3 * GSTGH * 2)       // 61440 bytes

// ---------------------------------------------------------------------------
__device__ __half g_hbuf0[TBc * Hc];
__device__ __half g_hbuf1[TBc * Hc];
__device__ float  g_G0[(size_t)TBc * H4c];
__device__ __half g_hs[TBc * Hc];           // h1 state (h1cur = hs[t])
__device__ __half g_h0[2 * BHc];            // layer-0 hidden ping-pong
__device__ __half g_zb[BHc];                // zero h1prev for t=0
__device__ __half g_wh[1310720];            // fp16 weights: Wi2|Wi3|Wih0|Wo1|Wo2
__device__ unsigned g_bar[NGRP];

// ---------------------------------------------------------------------------
__device__ __forceinline__ void mma16(float* d, const unsigned* a, const unsigned* b) {
    asm volatile("mma.sync.aligned.m16n8k16.row.col.f32.f16.f16.f32 "
        "{%0,%1,%2,%3}, {%4,%5,%6,%7}, {%8,%9}, {%0,%1,%2,%3};"
        : "+f"(d[0]), "+f"(d[1]), "+f"(d[2]), "+f"(d[3])
        : "r"(a[0]), "r"(a[1]), "r"(a[2]), "r"(a[3]), "r"(b[0]), "r"(b[1]));
}
__device__ __forceinline__ float sigmoidf_(float v) { return 1.f / (1.f + expf(-v)); }
__device__ __forceinline__ unsigned hrelu2(unsigned x) {
    __half2 h = __hmax2(*reinterpret_cast<__half2*>(&x), __float2half2_rn(0.f));
    return *reinterpret_cast<unsigned*>(&h);
}

__device__ __forceinline__ void cp_async16(void* dst, const void* src) {
    unsigned d = (unsigned)__cvta_generic_to_shared(dst);
    asm volatile("cp.async.ca.shared.global [%0], [%1], 16;\n" :: "r"(d), "l"(src));
}
__device__ __forceinline__ void cp_commit() {
    asm volatile("cp.async.commit_group;\n");
}
template<int N> __device__ __forceinline__ void cp_wait() {
    asm volatile("cp.async.wait_group %0;\n" :: "n"(N));
}
__device__ __forceinline__ void ldsm4h(unsigned* r, const __half* p) {
    unsigned a = (unsigned)__cvta_generic_to_shared(p);
    asm volatile("ldmatrix.sync.aligned.m8n8.x4.shared.b16 {%0,%1,%2,%3}, [%4];"
        : "=r"(r[0]), "=r"(r[1]), "=r"(r[2]), "=r"(r[3]) : "r"(a));
}

// Decoupled group barrier (recurrence)
__device__ __forceinline__ void bar_arrive(unsigned* ctr) {
    __syncthreads();
    if (threadIdx.x == 0)
        asm volatile("red.release.gpu.global.add.u32 [%0], 1;" :: "l"(ctr) : "memory");
}
__device__ __forceinline__ void bar_wait(unsigned* ctr, unsigned target) {
    if (threadIdx.x == 0) {
        unsigned v;
        do {
            asm volatile("ld.acquire.gpu.global.u32 %0, [%1];" : "=r"(v) : "l"(ctr) : "memory");
        } while (v < target);
    }
    __syncthreads();
}

// ---------------------------------------------------------------------------
// fp32 -> fp16 weight conversion
// ---------------------------------------------------------------------------
__global__ void wconv_k(const float* __restrict__ src, __half* __restrict__ dst, int n4) {
    int i = blockIdx.x * 256 + threadIdx.x;
    if (i < n4) {
        float4 v = ((const float4*)src)[i];
        ((__half2*)dst)[2 * i]     = __floats2half2_rn(v.x, v.y);
        ((__half2*)dst)[2 * i + 1] = __floats2half2_rn(v.z, v.w);
    }
}

// ---------------------------------------------------------------------------
// Kernel 1: u = half(relu(x @ Wi1^T + bi1))   [TB,6] -> [TB,256] fp16
// ---------------------------------------------------------------------------
__global__ void __launch_bounds__(256) in_mlp1_k(
    const float* __restrict__ x, const float* __restrict__ W,
    const float* __restrict__ b, __half* __restrict__ out)
{
    __shared__ float sW[Hc * LAGc];
    __shared__ float sb[Hc];
    __shared__ float sx[16 * LAGc];
    int tid = threadIdx.x;
    int m0  = blockIdx.x * 16;
    for (int i = tid; i < Hc * LAGc; i += 256) sW[i] = W[i];
    sb[tid] = b[tid];
    if (tid < 16 * LAGc) sx[tid] = x[m0 * LAGc + tid];
    __syncthreads();
    #pragma unroll
    for (int r = 0; r < 16; r++) {
        float acc = sb[tid];
        #pragma unroll
        for (int k = 0; k < LAGc; k++) acc += sx[r * LAGc + k] * sW[tid * LAGc + k];
        out[(m0 + r) * Hc + tid] = __float2half(fmaxf(acc, 0.f));
    }
}

// ---------------------------------------------------------------------------
// fp16 GEMM: C = act(A @ W^T + b1 [+b2]); block 128x128, K=256, BK=32,
// 3-stage cp.async, ldmatrix, m16n8k16 HMMA fp32-accum. 8 warps (2m x 4n).
// ---------------------------------------------------------------------------
template<bool RELU_OUT, bool PRE_RELU, bool OUT_HALF, bool HAS_B2>
__global__ void __launch_bounds__(256, 2) gemm_h16_k(
    const __half* __restrict__ A, const __half* __restrict__ W,
    const float* __restrict__ b1, const float* __restrict__ b2,
    void* __restrict__ Cv, int N)
{
    extern __shared__ __half gsmh[];
    const int K = 256;
    int tid = threadIdx.x, lane = tid & 31, wid = tid >> 5;
    int wm = wid & 1, wn = wid >> 1;
    int m0 = blockIdx.y * 128, n0 = blockIdx.x * 128;
    int qr = lane >> 2, qk = lane & 3;
    int l8 = lane & 7, lsel = (lane >> 3) & 1, lhalf = lane >> 4;

    const __half* Ab = A + (size_t)m0 * K;
    const __half* Wb = W + (size_t)n0 * K;

    int aoff[4], boff[2];
    #pragma unroll
    for (int mt = 0; mt < 4; mt++)
        aoff[mt] = (wm * 64 + mt * 16 + l8 + lsel * 8) * AHSTR + lhalf * 8;
    #pragma unroll
    for (int q = 0; q < 2; q++)
        boff[q] = ASTGH + (wn * 32 + q * 16 + lhalf * 8 + l8) * AHSTR + lsel * 8;

    const int nk = K / 32;   // 8
    auto stage = [&](int kt) {
        __half* S = gsmh + (kt % 3) * GSTGH;
        #pragma unroll
        for (int j = 0; j < 2; j++) {
            int i = tid + j * 256;
            int row = i >> 2, ko = (i & 3) * 8;
            cp_async16(S + row * AHSTR + ko, Ab + (size_t)row * K + kt * 32 + ko);
            cp_async16(S + ASTGH + row * AHSTR + ko, Wb + (size_t)row * K + kt * 32 + ko);
        }
        cp_commit();
    };

    stage(0);
    stage(1);

    float acc[4][4][4] = {};
    for (int kt = 0; kt < nk; kt++) {
        if (kt == nk - 1) cp_wait<0>(); else cp_wait<1>();
        __syncthreads();
        if (kt + 2 < nk) stage(kt + 2);
        const __half* S = gsmh + (kt % 3) * GSTGH;
        #pragma unroll
        for (int ks = 0; ks < 32; ks += 16) {
            unsigned ua[4][4], ub[2][4];
            #pragma unroll
            for (int mt = 0; mt < 4; mt++) {
                ldsm4h(ua[mt], S + aoff[mt] + ks);
                if (PRE_RELU) {
                    #pragma unroll
                    for (int i = 0; i < 4; i++) ua[mt][i] = hrelu2(ua[mt][i]);
                }
            }
            #pragma unroll
            for (int q = 0; q < 2; q++)
                ldsm4h(ub[q], S + boff[q] + ks);
            #pragma unroll
            for (int mt = 0; mt < 4; mt++)
                #pragma unroll
                for (int q = 0; q < 2; q++) {
                    mma16(acc[mt][2 * q],     ua[mt], ub[q]);
                    mma16(acc[mt][2 * q + 1], ua[mt], ub[q] + 2);
                }
        }
        __syncthreads();
    }

    #pragma unroll
    for (int nt = 0; nt < 4; nt++) {
        int col = n0 + wn * 32 + nt * 8 + 2 * qk;
        float bb0 = b1[col]     + (HAS_B2 ? b2[col]     : 0.f);
        float bb1 = b1[col + 1] + (HAS_B2 ? b2[col + 1] : 0.f);
        #pragma unroll
        for (int mt = 0; mt < 4; mt++) {
            int row = m0 + wm * 64 + mt * 16 + qr;
            float2 v0, v1;
            v0.x = acc[mt][nt][0] + bb0; v0.y = acc[mt][nt][1] + bb1;
            v1.x = acc[mt][nt][2] + bb0; v1.y = acc[mt][nt][3] + bb1;
            if (RELU_OUT) {
                v0.x=fmaxf(v0.x,0.f); v0.y=fmaxf(v0.y,0.f);
                v1.x=fmaxf(v1.x,0.f); v1.y=fmaxf(v1.y,0.f);
            }
            if (OUT_HALF) {
                __half* C = (__half*)Cv;
                *(__half2*)(C + (size_t)row * N + col)       = __floats2half2_rn(v0.x, v0.y);
                *(__half2*)(C + (size_t)(row + 8) * N + col) = __floats2half2_rn(v1.x, v1.y);
            } else {
                float* C = (float*)Cv;
                *(float2*)(C + (size_t)row * N + col)       = v0;
                *(float2*)(C + (size_t)(row + 8) * N + col) = v1;
            }
        }
    }
}

// ---------------------------------------------------------------------------
// Persistent LSTM helpers (fp16, K-chunk 32)
// ---------------------------------------------------------------------------
// Stage this warp's 16 rows x 32 halves (1 KB): 2 x cp.async16 per lane.
__device__ __forceinline__ void stage_warp_h(__half* Abuf, const __half* src_base,
                                             int wid, int lane) {
    #pragma unroll
    for (int i = 0; i < 2; i++) {
        int s = lane + i * 32;
        int row = wid * 16 + (s >> 2), kq = (s & 3) * 8;
        cp_async16(Abuf + row * AHSTR + kq, src_base + (size_t)row * Hc + kq);
    }
    cp_commit();
}

// MMA over one k32 chunk: 2 x (1 A-ldsm + 4 B-ldsm + 8 mma).
__device__ __forceinline__ void mma_chunk_h(
    const __half* Ab, int aoff, const __half* Wsm, int wstr, int woff, int kbase,
    float acc[8][4])
{
    #pragma unroll
    for (int ks = 0; ks < 32; ks += 16) {
        unsigned a[4];
        ldsm4h(a, Ab + aoff + ks);
        #pragma unroll
        for (int p = 0; p < 4; p++) {
            unsigned b[4];
            ldsm4h(b, Wsm + (size_t)(p * 16) * wstr + woff + kbase + ks);
            mma16(acc[2 * p],     a, b);
            mma16(acc[2 * p + 1], a, b + 2);
        }
    }
}

// ---------------------------------------------------------------------------
// Persistent recurrence: 128 timesteps, both layers, fp16 operands,
// fp32 accum + fp32 cell state; K-chunk 32 (L0: 8 chunks, L1: 16 chunks).
// ---------------------------------------------------------------------------
__global__ void __launch_bounds__(256, 1) lstm_persistent_k(
    const float* __restrict__ Whh0, const float* __restrict__ Wih1,
    const float* __restrict__ Whh1, const float* __restrict__ bih1,
    const float* __restrict__ bhh1, const float* __restrict__ G0,
    __half* __restrict__ h0buf, const __half* __restrict__ zbuf,
    __half* __restrict__ hs)
{
    extern __shared__ __half smh[];
    __half* W0   = smh;                              // [64][W0STRH]
    __half* W1   = smh + 64 * W0STRH;                // [64][W1STRH]
    __half* Abuf = smh + 64 * W0STRH + 64 * W1STRH;  // 3 x [128][AHSTR]

    int tid = threadIdx.x, lane = tid & 31, wid = tid >> 5;
    int qr = lane >> 2, qk = lane & 3;
    int grp = blockIdx.x >> 4, sub = blockIdx.x & 15;
    int m0  = grp * 128;
    int hc0 = sub * 16;

    // stage weights to smem as fp16 (once)
    for (int i = tid; i < 64 * 64; i += 256) {
        int n = i >> 6, kq = (i & 63) * 4;
        int gr = (n >> 4) * Hc + hc0 + (n & 15);
        float4 v = *(const float4*)(Whh0 + (size_t)gr * Hc + kq);
        __half2* dst = (__half2*)(W0 + n * W0STRH + kq);
        dst[0] = __floats2half2_rn(v.x, v.y);
        dst[1] = __floats2half2_rn(v.z, v.w);
    }
    for (int i = tid; i < 64 * 128; i += 256) {
        int n = i >> 7, kq = (i & 127) * 4;
        int gr = (n >> 4) * Hc + hc0 + (n & 15);
        const float* src = (kq < 256) ? (Wih1 + (size_t)gr * Hc + kq)
                                      : (Whh1 + (size_t)gr * Hc + (kq - 256));
        float4 v = *(const float4*)src;
        __half2* dst = (__half2*)(W1 + n * W1STRH + kq);
        dst[0] = __floats2half2_rn(v.x, v.y);
        dst[1] = __floats2half2_rn(v.z, v.w);
    }
    __syncthreads();

    int l8 = lane & 7, lsel = (lane >> 3) & 1, lhalf = lane >> 4;
    int aoff  = (wid * 16 + l8 + lsel * 8) * AHSTR + lhalf * 8;
    int woff0 = (lhalf * 8 + l8) * W0STRH + lsel * 8;
    int woff1 = (lhalf * 8 + l8) * W1STRH + lsel * 8;

    int wrow = wid * 16 + qr;
    float c0v[2][4] = {};
    float c1v[2][4] = {};
    float b1v[8][2];
    #pragma unroll
    for (int g = 0; g < 4; g++)
        #pragma unroll
        for (int h = 0; h < 2; h++)
            #pragma unroll
            for (int p = 0; p < 2; p++) {
                int n = g * Hc + hc0 + h * 8 + 2 * qk + p;
                b1v[g * 2 + h][p] = bih1[n] + bhh1[n];
            }

    unsigned* ctr = &g_bar[grp];

    for (int t = 0; t < Tc; t++) {
        const __half* h0prev = h0buf + (size_t)(t & 1) * BHc;
        __half*       h0cur  = h0buf + (size_t)((t + 1) & 1) * BHc;
        const __half* h1prev = (t == 0) ? zbuf : (hs + (size_t)(t - 1) * BHc);
        __half*       h1cur  = hs + (size_t)t * BHc;
        unsigned tB = (unsigned)(2 * t) * NSUB;
        unsigned tA = (unsigned)(2 * t + 1) * NSUB;

        // ================= layer 0 (K=256, 8 chunks of 32) =================
        float2 gI[2][2], gF[2][2], gG[2][2], gO[2][2];
        {
            const float* g0r0 = G0 + ((size_t)t * Bc + m0 + wrow) * H4c + hc0;
            #pragma unroll
            for (int r = 0; r < 2; r++) {
                const float* g0r = g0r0 + (size_t)r * 8 * H4c;
                #pragma unroll
                for (int h = 0; h < 2; h++) {
                    int hcl = h * 8 + 2 * qk;
                    gI[r][h] = *(const float2*)(g0r + hcl);
                    gF[r][h] = *(const float2*)(g0r + 256 + hcl);
                    gG[r][h] = *(const float2*)(g0r + 512 + hcl);
                    gO[r][h] = *(const float2*)(g0r + 768 + hcl);
                }
            }
        }

        float acc[8][4] = {};
        {
            const __half* A0p = h0prev + (size_t)m0 * Hc;
            stage_warp_h(Abuf + 0 * ABUFH, A0p + 0 * 32, wid, lane);
            stage_warp_h(Abuf + 1 * ABUFH, A0p + 1 * 32, wid, lane);
            #pragma unroll 4
            for (int c = 0; c < 8; c++) {
                if (c < 6) {
                    stage_warp_h(Abuf + ((c + 2) % 3) * ABUFH, A0p + (c + 2) * 32, wid, lane);
                    cp_wait<2>();
                } else if (c == 6) cp_wait<1>();
                else cp_wait<0>();
                __syncwarp();
                mma_chunk_h(Abuf + (c % 3) * ABUFH, aoff, W0, W0STRH, woff0, c * 32, acc);
            }
        }
        #pragma unroll
        for (int r = 0; r < 2; r++) {
            __half* hw = h0cur + (size_t)(m0 + wrow + r * 8) * Hc + hc0;
            #pragma unroll
            for (int h = 0; h < 2; h++) {
                int hcl = h * 8 + 2 * qk;
                float hv[2];
                #pragma unroll
                for (int p = 0; p < 2; p++) {
                    float gi = acc[0 + h][r * 2 + p] + (p ? gI[r][h].y : gI[r][h].x);
                    float gf = acc[2 + h][r * 2 + p] + (p ? gF[r][h].y : gF[r][h].x);
                    float gg = acc[4 + h][r * 2 + p] + (p ? gG[r][h].y : gG[r][h].x);
                    float go = acc[6 + h][r * 2 + p] + (p ? gO[r][h].y : gO[r][h].x);
                    float c  = c0v[r][h * 2 + p];
                    float c2 = sigmoidf_(gf) * c + sigmoidf_(gi) * tanhf(gg);
                    c0v[r][h * 2 + p] = c2;
                    hv[p] = sigmoidf_(go) * tanhf(c2);
                }
                *(__half2*)(hw + hcl) = __floats2half2_rn(hv[0], hv[1]);
            }
        }
        bar_arrive(ctr);                 // phase 2t+1

        // ================= layer 1 (K=512, 16 chunks of 32) =================
        #pragma unroll
        for (int nf = 0; nf < 8; nf++)
            #pragma unroll
            for (int j = 0; j < 4; j++) acc[nf][j] = 0.f;

        bar_wait(ctr, tB);
        {
            const __half* A1 = h1prev + (size_t)m0 * Hc;
            const __half* A0 = h0cur + (size_t)m0 * Hc;
            stage_warp_h(Abuf + 0 * ABUFH, A1 + 0 * 32, wid, lane);
            stage_warp_h(Abuf + 1 * ABUFH, A1 + 1 * 32, wid, lane);
            #pragma unroll 4
            for (int c = 0; c < 16; c++) {
                if (c == 6) bar_wait(ctr, tA);    // before staging h0cur (chunk 8)
                if (c < 14) {
                    int cn = c + 2;
                    const __half* src = (cn < 8) ? (A1 + cn * 32) : (A0 + (cn - 8) * 32);
                    stage_warp_h(Abuf + (cn % 3) * ABUFH, src, wid, lane);
                    cp_wait<2>();
                } else if (c == 14) cp_wait<1>();
                else cp_wait<0>();
                __syncwarp();
                int kb = (c < 8) ? (256 + c * 32) : ((c - 8) * 32);
                mma_chunk_h(Abuf + (c % 3) * ABUFH, aoff, W1, W1STRH, woff1, kb, acc);
            }
        }
        #pragma unroll
        for (int r = 0; r < 2; r++) {
            __half* hw = h1cur + (size_t)(m0 + wrow + r * 8) * Hc + hc0;
            #pragma unroll
            for (int h = 0; h < 2; h++) {
                int hcl = h * 8 + 2 * qk;
                float hv[2];
                #pragma unroll
                for (int p = 0; p < 2; p++) {
                    float gi = acc[0 + h][r * 2 + p] + b1v[0 + h][p];
                    float gf = acc[2 + h][r * 2 + p] + b1v[2 + h][p];
                    float gg = acc[4 + h][r * 2 + p] + b1v[4 + h][p];
                    float go = acc[6 + h][r * 2 + p] + b1v[6 + h][p];
                    float c  = c1v[r][h * 2 + p];
                    float c2 = sigmoidf_(gf) * c + sigmoidf_(gi) * tanhf(gg);
                    c1v[r][h * 2 + p] = c2;
                    hv[p] = sigmoidf_(go) * tanhf(c2);
                }
                *(__half2*)(hw + hcl) = __floats2half2_rn(hv[0], hv[1]);
            }
        }
        bar_arrive(ctr);                 // phase 2t+2
    }
}

// ---------------------------------------------------------------------------
// Final layer: y = A @ Wo3^T + bo3  (N=6, K=256). A fp16, math fp32.
// ---------------------------------------------------------------------------
__global__ void __launch_bounds__(256) out_mlp3_k(
    const __half* __restrict__ A, const float* __restrict__ W,
    const float* __restrict__ b, float* __restrict__ out)
{
    __shared__ float sW[LAGc * Hc];
    __shared__ float sb[LAGc];
    int tid = threadIdx.x;
    for (int i = tid; i < LAGc * Hc; i += 256) sW[i] = W[i];
    if (tid < LAGc) sb[tid] = b[tid];
    __syncthreads();
    int w = tid >> 5, lane = tid & 31;
    int m = blockIdx.x * 8 + w;
    float a[8];
    #pragma unroll
    for (int j = 0; j < 8; j++) a[j] = __half2float(A[(size_t)m * Hc + lane + 32 * j]);
    #pragma unroll
    for (int n = 0; n < LAGc; n++) {
        float s = 0.f;
        #pragma unroll
        for (int j = 0; j < 8; j++) s += a[j] * sW[n * Hc + lane + 32 * j];
        #pragma unroll
        for (int o = 16; o > 0; o >>= 1) s += __shfl_xor_sync(0xffffffff, s, o);
        if (lane == n) out[m * LAGc + n] = s + sb[n];
    }
}

// ---------------------------------------------------------------------------
extern "C" void kernel_launch(void* const* d_in, const int* in_sizes, int n_in,
                              void* d_out, int out_size)
{
    const float* x    = (const float*)d_in[0];
    const float* Wi1  = (const float*)d_in[1];
    const float* bi1  = (const float*)d_in[2];
    const float* Wi2  = (const float*)d_in[3];
    const float* bi2  = (const float*)d_in[4];
    const float* Wi3  = (const float*)d_in[5];
    const float* bi3  = (const float*)d_in[6];
    const float* Wih0 = (const float*)d_in[7];
    const float* Whh0 = (const float*)d_in[8];
    const float* bih0 = (const float*)d_in[9];
    const float* bhh0 = (const float*)d_in[10];
    const float* Wih1 = (const float*)d_in[11];
    const float* Whh1 = (const float*)d_in[12];
    const float* bih1 = (const float*)d_in[13];
    const float* bhh1 = (const float*)d_in[14];
    const float* Wo1  = (const float*)d_in[15];
    const float* bo1  = (const float*)d_in[16];
    const float* Wo2  = (const float*)d_in[17];
    const float* bo2  = (const float*)d_in[18];
    const float* Wo3  = (const float*)d_in[19];
    const float* bo3  = (const float*)d_in[20];
    float* out = (float*)d_out;

    __half *hbuf0, *hbuf1, *hs, *h0, *zb, *wh;
    float *G0;
    unsigned* bar;
    cudaGetSymbolAddress((void**)&hbuf0, g_hbuf0);
    cudaGetSymbolAddress((void**)&hbuf1, g_hbuf1);
    cudaGetSymbolAddress((void**)&G0,    g_G0);
    cudaGetSymbolAddress((void**)&hs,    g_hs);
    cudaGetSymbolAddress((void**)&h0,    g_h0);
    cudaGetSymbolAddress((void**)&zb,    g_zb);
    cudaGetSymbolAddress((void**)&wh,    g_wh);
    cudaGetSymbolAddress((void**)&bar,   g_bar);

    __half* Wi2h  = wh;                 // 65536
    __half* Wi3h  = wh + 65536;         // 65536
    __half* Wih0h = wh + 131072;        // 1048576
    __half* Wo1h  = wh + 1179648;       // 65536
    __half* Wo2h  = wh + 1245184;       // 65536

    cudaFuncSetAttribute(lstm_persistent_k,
                         cudaFuncAttributeMaxDynamicSharedMemorySize, SMEM_P);
    cudaFuncSetAttribute(gemm_h16_k<true,  false, true,  false>,
                         cudaFuncAttributeMaxDynamicSharedMemorySize, SMEM_GH);
    cudaFuncSetAttribute(gemm_h16_k<false, false, false, true >,
                         cudaFuncAttributeMaxDynamicSharedMemorySize, SMEM_GH);
    cudaFuncSetAttribute(gemm_h16_k<true,  true,  true,  false>,
                         cudaFuncAttributeMaxDynamicSharedMemorySize, SMEM_GH);

    cudaMemsetAsync(h0, 0, 2 * BHc * sizeof(__half));
    cudaMemsetAsync(zb, 0, BHc * sizeof(__half));
    cudaMemsetAsync(bar, 0, NGRP * sizeof(unsigned));

    // fp16 weight copies for the GEMM chain
    wconv_k<<<64,   256>>>(Wi2,  Wi2h,  65536 / 4);
    wconv_k<<<64,   256>>>(Wi3,  Wi3h,  65536 / 4);
    wconv_k<<<1024, 256>>>(Wih0, Wih0h, 1048576 / 4);
    wconv_k<<<64,   256>>>(Wo1,  Wo1h,  65536 / 4);
    wconv_k<<<64,   256>>>(Wo2,  Wo2h,  65536 / 4);

    // Input MLP
    in_mlp1_k<<<TBc / 16, 256>>>(x, Wi1, bi1, hbuf0);
    dim3 gH(Hc / 128, TBc / 128);      // (2, 1024)
    gemm_h16_k<true, false, true, false><<<gH, 256, SMEM_GH>>>(hbuf0, Wi2h, bi2, nullptr, hbuf1, Hc);
    gemm_h16_k<true, false, true, false><<<gH, 256, SMEM_GH>>>(hbuf1, Wi3h, bi3, nullptr, hbuf0, Hc);

    // Layer-0 input projection for ALL timesteps (fp32 output + both biases)
    dim3 gG(H4c / 128, TBc / 128);     // (8, 1024)
    gemm_h16_k<false, false, false, true><<<gG, 256, SMEM_GH>>>(hbuf0, Wih0h, bih0, bhh0, G0, H4c);

    // Entire recurrence in one persistent launch
    lstm_persistent_k<<<NBLK, 256, SMEM_P>>>(Whh0, Wih1, Whh1, bih1, bhh1,
                                             G0, h0, zb, hs);

    // Output MLP (PRE_RELU on hs)
    gemm_h16_k<true, true,  true, false><<<gH, 256, SMEM_GH>>>(hs,    Wo1h, bo1, nullptr, hbuf0, Hc);
    gemm_h16_k<true, false, true, false><<<gH, 256, SMEM_GH>>>(hbuf0, Wo2h, bo2, nullptr, hbuf1, Hc);
    out_mlp3_k<<<TBc / 8, 256>>>(hbuf1, Wo3, bo3, out);
}

// round 13
// speedup vs baseline: 1.2979x; 1.2979x over previous
#include <cuda_runtime.h>
#include <cuda_fp16.h>
#include <math.h>

// Problem constants
#define Tc   128
#define Bc   1024
#define LAGc 6
#define Hc   256
#define H4c  1024
#define TBc  (Tc * Bc)      // 131072
#define BHc  (Bc * Hc)      // 262144

// Persistent recurrence kernel geometry (fp16, K-chunk 16, 4-deep pipeline)
#define NGRP   8
#define NSUB   16
#define NBLK   (NGRP * NSUB)
#define W0STRH 264          // smem row stride (halves) layer0 weights (K=256)
#define W1STRH 520          // layer1 (K=512)
#define AHSTR  24           // A staging row stride (halves), 48B, conflict-free
#define ABUFH  (128 * AHSTR)  // halves per A buffer (3072)
#define NABUF  4
#define SMEM_P ((64 * W0STRH + 64 * W1STRH + NABUF * ABUFH) * 2)   // 124928 bytes

// fp16 GEMM pipeline (round-11 proven): 3 stages x (A 128x16 + B 128x16)
#define HSTG   (128 * AHSTR)          // 3072 halves per operand
#define GSTGH  (2 * HSTG)             // 6144 halves per stage
#define SMEM_GH (3 * GSTGH * 2)       // 36864 bytes

// ---------------------------------------------------------------------------
__device__ __half g_hbuf0[TBc * Hc];
__device__ __half g_hbuf1[TBc * Hc];
__device__ float  g_G0[(size_t)TBc * H4c];
__device__ __half g_hs[TBc * Hc];           // h1 state (h1cur = hs[t])
__device__ __half g_h0[2 * BHc];            // layer-0 hidden ping-pong
__device__ __half g_wh[1310720];            // fp16 weights: Wi2|Wi3|Wih0|Wo1|Wo2
__device__ unsigned g_bar[NGRP];

// ---------------------------------------------------------------------------
__device__ __forceinline__ void mma16(float* d, const unsigned* a, const unsigned* b) {
    asm volatile("mma.sync.aligned.m16n8k16.row.col.f32.f16.f16.f32 "
        "{%0,%1,%2,%3}, {%4,%5,%6,%7}, {%8,%9}, {%0,%1,%2,%3};"
        : "+f"(d[0]), "+f"(d[1]), "+f"(d[2]), "+f"(d[3])
        : "r"(a[0]), "r"(a[1]), "r"(a[2]), "r"(a[3]), "r"(b[0]), "r"(b[1]));
}
__device__ __forceinline__ float sigmoidf_(float v) { return 1.f / (1.f + expf(-v)); }
__device__ __forceinline__ unsigned hrelu2(unsigned x) {
    __half2 h = __hmax2(*reinterpret_cast<__half2*>(&x), __float2half2_rn(0.f));
    return *reinterpret_cast<unsigned*>(&h);
}

__device__ __forceinline__ void cp_async16(void* dst, const void* src) {
    unsigned d = (unsigned)__cvta_generic_to_shared(dst);
    asm volatile("cp.async.ca.shared.global [%0], [%1], 16;\n" :: "r"(d), "l"(src));
}
__device__ __forceinline__ void cp_commit() {
    asm volatile("cp.async.commit_group;\n");
}
template<int N> __device__ __forceinline__ void cp_wait() {
    asm volatile("cp.async.wait_group %0;\n" :: "n"(N));
}
__device__ __forceinline__ void ldsm4h(unsigned* r, const __half* p) {
    unsigned a = (unsigned)__cvta_generic_to_shared(p);
    asm volatile("ldmatrix.sync.aligned.m8n8.x4.shared.b16 {%0,%1,%2,%3}, [%4];"
        : "=r"(r[0]), "=r"(r[1]), "=r"(r[2]), "=r"(r[3]) : "r"(a));
}

// Decoupled group barrier (recurrence)
__device__ __forceinline__ void bar_arrive(unsigned* ctr) {
    __syncthreads();
    if (threadIdx.x == 0)
        asm volatile("red.release.gpu.global.add.u32 [%0], 1;" :: "l"(ctr) : "memory");
}
__device__ __forceinline__ void bar_wait(unsigned* ctr, unsigned target) {
    if (threadIdx.x == 0) {
        unsigned v;
        do {
            asm volatile("ld.acquire.gpu.global.u32 %0, [%1];" : "=r"(v) : "l"(ctr) : "memory");
        } while (v < target);
    }
    __syncthreads();
}

// ---------------------------------------------------------------------------
// fp32 -> fp16 weight conversion
// ---------------------------------------------------------------------------
__global__ void wconv_k(const float* __restrict__ src, __half* __restrict__ dst, int n4) {
    int i = blockIdx.x * 256 + threadIdx.x;
    if (i < n4) {
        float4 v = ((const float4*)src)[i];
        ((__half2*)dst)[2 * i]     = __floats2half2_rn(v.x, v.y);
        ((__half2*)dst)[2 * i + 1] = __floats2half2_rn(v.z, v.w);
    }
}

// ---------------------------------------------------------------------------
// Kernel 1: u = half(relu(x @ Wi1^T + bi1))   [TB,6] -> [TB,256] fp16
// ---------------------------------------------------------------------------
__global__ void __launch_bounds__(256) in_mlp1_k(
    const float* __restrict__ x, const float* __restrict__ W,
    const float* __restrict__ b, __half* __restrict__ out)
{
    __shared__ float sW[Hc * LAGc];
    __shared__ float sb[Hc];
    __shared__ float sx[16 * LAGc];
    int tid = threadIdx.x;
    int m0  = blockIdx.x * 16;
    for (int i = tid; i < Hc * LAGc; i += 256) sW[i] = W[i];
    sb[tid] = b[tid];
    if (tid < 16 * LAGc) sx[tid] = x[m0 * LAGc + tid];
    __syncthreads();
    #pragma unroll
    for (int r = 0; r < 16; r++) {
        float acc = sb[tid];
        #pragma unroll
        for (int k = 0; k < LAGc; k++) acc += sx[r * LAGc + k] * sW[tid * LAGc + k];
        out[(m0 + r) * Hc + tid] = __float2half(fmaxf(acc, 0.f));
    }
}

// ---------------------------------------------------------------------------
// fp16 GEMM (round-11 proven, byte-for-byte): block 128x128, K=256, BK=16,
// 3-stage cp.async, ldmatrix, m16n8k16 HMMA fp32-accum. 8 warps (2m x 4n).
// ---------------------------------------------------------------------------
template<bool RELU_OUT, bool PRE_RELU, bool OUT_HALF, bool HAS_B2>
__global__ void __launch_bounds__(256, 2) gemm_h16_k(
    const __half* __restrict__ A, const __half* __restrict__ W,
    const float* __restrict__ b1, const float* __restrict__ b2,
    void* __restrict__ Cv, int N)
{
    extern __shared__ __half gsmh[];
    const int K = 256;
    int tid = threadIdx.x, lane = tid & 31, wid = tid >> 5;
    int wm = wid & 1, wn = wid >> 1;
    int m0 = blockIdx.y * 128, n0 = blockIdx.x * 128;
    int qr = lane >> 2, qk = lane & 3;
    int l8 = lane & 7, lsel = (lane >> 3) & 1, lhalf = lane >> 4;

    const __half* Ab = A + (size_t)m0 * K;
    const __half* Wb = W + (size_t)n0 * K;

    int srow = tid >> 1, sko = (tid & 1) * 8;   // halves

    int aoff[4], boff[2];
    #pragma unroll
    for (int mt = 0; mt < 4; mt++)
        aoff[mt] = (wm * 64 + mt * 16 + l8 + lsel * 8) * AHSTR + lhalf * 8;
    #pragma unroll
    for (int q = 0; q < 2; q++)
        boff[q] = HSTG + (wn * 32 + q * 16 + lhalf * 8 + l8) * AHSTR + lsel * 8;

    const int nk = K / 16;   // 16
    auto stage = [&](int kt) {
        __half* S = gsmh + (kt % 3) * GSTGH;
        cp_async16(S + srow * AHSTR + sko, Ab + (size_t)srow * K + kt * 16 + sko);
        cp_async16(S + HSTG + srow * AHSTR + sko, Wb + (size_t)srow * K + kt * 16 + sko);
        cp_commit();
    };

    stage(0);
    stage(1);

    float acc[4][4][4] = {};
    for (int kt = 0; kt < nk; kt++) {
        if (kt == nk - 1) cp_wait<0>(); else cp_wait<1>();
        __syncthreads();
        if (kt + 2 < nk) stage(kt + 2);
        const __half* S = gsmh + (kt % 3) * GSTGH;
        unsigned ua[4][4], ub[2][4];
        #pragma unroll
        for (int mt = 0; mt < 4; mt++) {
            ldsm4h(ua[mt], S + aoff[mt]);
            if (PRE_RELU) {
                #pragma unroll
                for (int i = 0; i < 4; i++) ua[mt][i] = hrelu2(ua[mt][i]);
            }
        }
        #pragma unroll
        for (int q = 0; q < 2; q++)
            ldsm4h(ub[q], S + boff[q]);
        #pragma unroll
        for (int mt = 0; mt < 4; mt++)
            #pragma unroll
            for (int q = 0; q < 2; q++) {
                mma16(acc[mt][2 * q],     ua[mt], ub[q]);
                mma16(acc[mt][2 * q + 1], ua[mt], ub[q] + 2);
            }
        __syncthreads();
    }

    #pragma unroll
    for (int nt = 0; nt < 4; nt++) {
        int col = n0 + wn * 32 + nt * 8 + 2 * qk;
        float bb0 = b1[col]     + (HAS_B2 ? b2[col]     : 0.f);
        float bb1 = b1[col + 1] + (HAS_B2 ? b2[col + 1] : 0.f);
        #pragma unroll
        for (int mt = 0; mt < 4; mt++) {
            int row = m0 + wm * 64 + mt * 16 + qr;
            float2 v0, v1;
            v0.x = acc[mt][nt][0] + bb0; v0.y = acc[mt][nt][1] + bb1;
            v1.x = acc[mt][nt][2] + bb0; v1.y = acc[mt][nt][3] + bb1;
            if (RELU_OUT) {
                v0.x=fmaxf(v0.x,0.f); v0.y=fmaxf(v0.y,0.f);
                v1.x=fmaxf(v1.x,0.f); v1.y=fmaxf(v1.y,0.f);
            }
            if (OUT_HALF) {
                __half* C = (__half*)Cv;
                *(__half2*)(C + (size_t)row * N + col)       = __floats2half2_rn(v0.x, v0.y);
                *(__half2*)(C + (size_t)(row + 8) * N + col) = __floats2half2_rn(v1.x, v1.y);
            } else {
                float* C = (float*)Cv;
                *(float2*)(C + (size_t)row * N + col)       = v0;
                *(float2*)(C + (size_t)(row + 8) * N + col) = v1;
            }
        }
    }
}

// ---------------------------------------------------------------------------
// Persistent LSTM helpers (fp16, chunk 16)
// ---------------------------------------------------------------------------
__device__ __forceinline__ void stage_warp_h(__half* Abuf, const __half* src_base,
                                             int wid, int lane) {
    int row = wid * 16 + (lane >> 1), kq = (lane & 1) * 8;
    cp_async16(Abuf + row * AHSTR + kq, src_base + (size_t)row * Hc + kq);
    cp_commit();
}

// MMA over one k16 chunk: 1 A-ldsm + 4 B-ldsm + 8 mma.
__device__ __forceinline__ void mma_chunk_h(
    const __half* Ab, int aoff, const __half* Wsm, int wstr, int woff, int kbase,
    float acc[8][4])
{
    unsigned a[4];
    ldsm4h(a, Ab + aoff);
    #pragma unroll
    for (int p = 0; p < 4; p++) {
        unsigned b[4];
        ldsm4h(b, Wsm + (size_t)(p * 16) * wstr + woff + kbase);
        mma16(acc[2 * p],     a, b);
        mma16(acc[2 * p + 1], a, b + 2);
    }
}

// ---------------------------------------------------------------------------
// Persistent recurrence: chunk 16, 4 A-buffers, lookahead 3.
// fp16 operands, fp32 accum + fp32 cell state. t=0 skips the h1prev half.
// ---------------------------------------------------------------------------
__global__ void __launch_bounds__(256, 1) lstm_persistent_k(
    const float* __restrict__ Whh0, const float* __restrict__ Wih1,
    const float* __restrict__ Whh1, const float* __restrict__ bih1,
    const float* __restrict__ bhh1, const float* __restrict__ G0,
    __half* __restrict__ h0buf, __half* __restrict__ hs)
{
    extern __shared__ __half smh[];
    __half* W0   = smh;                              // [64][W0STRH]
    __half* W1   = smh + 64 * W0STRH;                // [64][W1STRH]
    __half* Abuf = smh + 64 * W0STRH + 64 * W1STRH;  // 4 x [128][AHSTR]

    int tid = threadIdx.x, lane = tid & 31, wid = tid >> 5;
    int qr = lane >> 2, qk = lane & 3;
    int grp = blockIdx.x >> 4, sub = blockIdx.x & 15;
    int m0  = grp * 128;
    int hc0 = sub * 16;

    // stage weights to smem as fp16 (once)
    for (int i = tid; i < 64 * 64; i += 256) {
        int n = i >> 6, kq = (i & 63) * 4;
        int gr = (n >> 4) * Hc + hc0 + (n & 15);
        float4 v = *(const float4*)(Whh0 + (size_t)gr * Hc + kq);
        __half2* dst = (__half2*)(W0 + n * W0STRH + kq);
        dst[0] = __floats2half2_rn(v.x, v.y);
        dst[1] = __floats2half2_rn(v.z, v.w);
    }
    for (int i = tid; i < 64 * 128; i += 256) {
        int n = i >> 7, kq = (i & 127) * 4;
        int gr = (n >> 4) * Hc + hc0 + (n & 15);
        const float* src = (kq < 256) ? (Wih1 + (size_t)gr * Hc + kq)
                                      : (Whh1 + (size_t)gr * Hc + (kq - 256));
        float4 v = *(const float4*)src;
        __half2* dst = (__half2*)(W1 + n * W1STRH + kq);
        dst[0] = __floats2half2_rn(v.x, v.y);
        dst[1] = __floats2half2_rn(v.z, v.w);
    }
    __syncthreads();

    int l8 = lane & 7, lsel = (lane >> 3) & 1, lhalf = lane >> 4;
    int aoff  = (wid * 16 + l8 + lsel * 8) * AHSTR + lhalf * 8;
    int woff0 = (lhalf * 8 + l8) * W0STRH + lsel * 8;
    int woff1 = (lhalf * 8 + l8) * W1STRH + lsel * 8;

    int wrow = wid * 16 + qr;
    float c0v[2][4] = {};
    float c1v[2][4] = {};
    float b1v[8][2];
    #pragma unroll
    for (int g = 0; g < 4; g++)
        #pragma unroll
        for (int h = 0; h < 2; h++)
            #pragma unroll
            for (int p = 0; p < 2; p++) {
                int n = g * Hc + hc0 + h * 8 + 2 * qk + p;
                b1v[g * 2 + h][p] = bih1[n] + bhh1[n];
            }

    unsigned* ctr = &g_bar[grp];

    for (int t = 0; t < Tc; t++) {
        const __half* h0prev = h0buf + (size_t)(t & 1) * BHc;
        __half*       h0cur  = h0buf + (size_t)((t + 1) & 1) * BHc;
        const __half* h1prev = hs + (size_t)(t - 1) * BHc;   // valid for t>0
        __half*       h1cur  = hs + (size_t)t * BHc;
        unsigned tB = (unsigned)(2 * t) * NSUB;
        unsigned tA = (unsigned)(2 * t + 1) * NSUB;

        // ================= layer 0 (K=256, 16 chunks; skipped staging at t=0
        // would break h0prev which is zeroed memory — h0prev valid always) ====
        float2 gI[2][2], gF[2][2], gG[2][2], gO[2][2];
        {
            const float* g0r0 = G0 + ((size_t)t * Bc + m0 + wrow) * H4c + hc0;
            #pragma unroll
            for (int r = 0; r < 2; r++) {
                const float* g0r = g0r0 + (size_t)r * 8 * H4c;
                #pragma unroll
                for (int h = 0; h < 2; h++) {
                    int hcl = h * 8 + 2 * qk;
                    gI[r][h] = *(const float2*)(g0r + hcl);
                    gF[r][h] = *(const float2*)(g0r + 256 + hcl);
                    gG[r][h] = *(const float2*)(g0r + 512 + hcl);
                    gO[r][h] = *(const float2*)(g0r + 768 + hcl);
                }
            }
        }

        float acc[8][4] = {};
        {
            const __half* A0p = h0prev + (size_t)m0 * Hc;
            stage_warp_h(Abuf + 0 * ABUFH, A0p + 0 * 16, wid, lane);
            stage_warp_h(Abuf + 1 * ABUFH, A0p + 1 * 16, wid, lane);
            stage_warp_h(Abuf + 2 * ABUFH, A0p + 2 * 16, wid, lane);
            #pragma unroll 4
            for (int c = 0; c < 16; c++) {
                if (c < 13) {
                    stage_warp_h(Abuf + ((c + 3) & 3) * ABUFH, A0p + (c + 3) * 16, wid, lane);
                    cp_wait<3>();
                } else if (c == 13) cp_wait<2>();
                else if (c == 14) cp_wait<1>();
                else cp_wait<0>();
                __syncwarp();
                mma_chunk_h(Abuf + (c & 3) * ABUFH, aoff, W0, W0STRH, woff0, c * 16, acc);
            }
        }
        #pragma unroll
        for (int r = 0; r < 2; r++) {
            __half* hw = h0cur + (size_t)(m0 + wrow + r * 8) * Hc + hc0;
            #pragma unroll
            for (int h = 0; h < 2; h++) {
                int hcl = h * 8 + 2 * qk;
                float hv[2];
                #pragma unroll
                for (int p = 0; p < 2; p++) {
                    float gi = acc[0 + h][r * 2 + p] + (p ? gI[r][h].y : gI[r][h].x);
                    float gf = acc[2 + h][r * 2 + p] + (p ? gF[r][h].y : gF[r][h].x);
                    float gg = acc[4 + h][r * 2 + p] + (p ? gG[r][h].y : gG[r][h].x);
                    float go = acc[6 + h][r * 2 + p] + (p ? gO[r][h].y : gO[r][h].x);
                    float c  = c0v[r][h * 2 + p];
                    float c2 = sigmoidf_(gf) * c + sigmoidf_(gi) * tanhf(gg);
                    c0v[r][h * 2 + p] = c2;
                    hv[p] = sigmoidf_(go) * tanhf(c2);
                }
                *(__half2*)(hw + hcl) = __floats2half2_rn(hv[0], hv[1]);
            }
        }
        bar_arrive(ctr);                 // phase 2t+1

        // ================= layer 1 (K=512, 32 chunks; t=0 starts at 16) =====
        #pragma unroll
        for (int nf = 0; nf < 8; nf++)
            #pragma unroll
            for (int j = 0; j < 4; j++) acc[nf][j] = 0.f;

        {
            const __half* A0 = h0cur + (size_t)m0 * Hc;
            const __half* A1 = h1prev + (size_t)m0 * Hc;
            int cstart;
            if (t == 0) {
                cstart = 16;
                bar_wait(ctr, tA);       // need h0cur immediately
            } else {
                cstart = 0;
                bar_wait(ctr, tB);       // normally already satisfied
            }
            auto srcof = [&](int cn) {
                return (cn < 16) ? (A1 + cn * 16) : (A0 + (cn - 16) * 16);
            };
            stage_warp_h(Abuf + 0 * ABUFH, srcof(cstart),     wid, lane);
            stage_warp_h(Abuf + 1 * ABUFH, srcof(cstart + 1), wid, lane);
            stage_warp_h(Abuf + 2 * ABUFH, srcof(cstart + 2), wid, lane);
            for (int c = cstart; c < 32; c++) {
                if (c < 29) {
                    if (c == 13) bar_wait(ctr, tA);   // before staging h0cur (chunk 16)
                    stage_warp_h(Abuf + ((c + 3 - cstart) & 3) * ABUFH, srcof(c + 3), wid, lane);
                    cp_wait<3>();
                } else if (c == 29) cp_wait<2>();
                else if (c == 30) cp_wait<1>();
                else cp_wait<0>();
                __syncwarp();
                int kb = (c < 16) ? (256 + c * 16) : ((c - 16) * 16);
                mma_chunk_h(Abuf + ((c - cstart) & 3) * ABUFH, aoff, W1, W1STRH, woff1, kb, acc);
            }
        }
        #pragma unroll
        for (int r = 0; r < 2; r++) {
            __half* hw = h1cur + (size_t)(m0 + wrow + r * 8) * Hc + hc0;
            #pragma unroll
            for (int h = 0; h < 2; h++) {
                int hcl = h * 8 + 2 * qk;
                float hv[2];
                #pragma unroll
                for (int p = 0; p < 2; p++) {
                    float gi = acc[0 + h][r * 2 + p] + b1v[0 + h][p];
                    float gf = acc[2 + h][r * 2 + p] + b1v[2 + h][p];
                    float gg = acc[4 + h][r * 2 + p] + b1v[4 + h][p];
                    float go = acc[6 + h][r * 2 + p] + b1v[6 + h][p];
                    float c  = c1v[r][h * 2 + p];
                    float c2 = sigmoidf_(gf) * c + sigmoidf_(gi) * tanhf(gg);
                    c1v[r][h * 2 + p] = c2;
                    hv[p] = sigmoidf_(go) * tanhf(c2);
                }
                *(__half2*)(hw + hcl) = __floats2half2_rn(hv[0], hv[1]);
            }
        }
        bar_arrive(ctr);                 // phase 2t+2
    }
}

// ---------------------------------------------------------------------------
// Final layer: y = A @ Wo3^T + bo3  (N=6, K=256). A fp16, math fp32.
// ---------------------------------------------------------------------------
__global__ void __launch_bounds__(256) out_mlp3_k(
    const __half* __restrict__ A, const float* __restrict__ W,
    const float* __restrict__ b, float* __restrict__ out)
{
    __shared__ float sW[LAGc * Hc];
    __shared__ float sb[LAGc];
    int tid = threadIdx.x;
    for (int i = tid; i < LAGc * Hc; i += 256) sW[i] = W[i];
    if (tid < LAGc) sb[tid] = b[tid];
    __syncthreads();
    int w = tid >> 5, lane = tid & 31;
    int m = blockIdx.x * 8 + w;
    float a[8];
    #pragma unroll
    for (int j = 0; j < 8; j++) a[j] = __half2float(A[(size_t)m * Hc + lane + 32 * j]);
    #pragma unroll
    for (int n = 0; n < LAGc; n++) {
        float s = 0.f;
        #pragma unroll
        for (int j = 0; j < 8; j++) s += a[j] * sW[n * Hc + lane + 32 * j];
        #pragma unroll
        for (int o = 16; o > 0; o >>= 1) s += __shfl_xor_sync(0xffffffff, s, o);
        if (lane == n) out[m * LAGc + n] = s + sb[n];
    }
}

// ---------------------------------------------------------------------------
extern "C" void kernel_launch(void* const* d_in, const int* in_sizes, int n_in,
                              void* d_out, int out_size)
{
    const float* x    = (const float*)d_in[0];
    const float* Wi1  = (const float*)d_in[1];
    const float* bi1  = (const float*)d_in[2];
    const float* Wi2  = (const float*)d_in[3];
    const float* bi2  = (const float*)d_in[4];
    const float* Wi3  = (const float*)d_in[5];
    const float* bi3  = (const float*)d_in[6];
    const float* Wih0 = (const float*)d_in[7];
    const float* Whh0 = (const float*)d_in[8];
    const float* bih0 = (const float*)d_in[9];
    const float* bhh0 = (const float*)d_in[10];
    const float* Wih1 = (const float*)d_in[11];
    const float* Whh1 = (const float*)d_in[12];
    const float* bih1 = (const float*)d_in[13];
    const float* bhh1 = (const float*)d_in[14];
    const float* Wo1  = (const float*)d_in[15];
    const float* bo1  = (const float*)d_in[16];
    const float* Wo2  = (const float*)d_in[17];
    const float* bo2  = (const float*)d_in[18];
    const float* Wo3  = (const float*)d_in[19];
    const float* bo3  = (const float*)d_in[20];
    float* out = (float*)d_out;

    __half *hbuf0, *hbuf1, *hs, *h0, *wh;
    float *G0;
    unsigned* bar;
    cudaGetSymbolAddress((void**)&hbuf0, g_hbuf0);
    cudaGetSymbolAddress((void**)&hbuf1, g_hbuf1);
    cudaGetSymbolAddress((void**)&G0,    g_G0);
    cudaGetSymbolAddress((void**)&hs,    g_hs);
    cudaGetSymbolAddress((void**)&h0,    g_h0);
    cudaGetSymbolAddress((void**)&wh,    g_wh);
    cudaGetSymbolAddress((void**)&bar,   g_bar);

    __half* Wi2h  = wh;                 // 65536
    __half* Wi3h  = wh + 65536;         // 65536
    __half* Wih0h = wh + 131072;        // 1048576
    __half* Wo1h  = wh + 1179648;       // 65536
    __half* Wo2h  = wh + 1245184;       // 65536

    cudaFuncSetAttribute(lstm_persistent_k,
                         cudaFuncAttributeMaxDynamicSharedMemorySize, SMEM_P);
    cudaFuncSetAttribute(gemm_h16_k<true,  false, true,  false>,
                         cudaFuncAttributeMaxDynamicSharedMemorySize, SMEM_GH);
    cudaFuncSetAttribute(gemm_h16_k<false, false, false, true >,
                         cudaFuncAttributeMaxDynamicSharedMemorySize, SMEM_GH);
    cudaFuncSetAttribute(gemm_h16_k<true,  true,  true,  false>,
                         cudaFuncAttributeMaxDynamicSharedMemorySize, SMEM_GH);

    cudaMemsetAsync(h0, 0, 2 * BHc * sizeof(__half));
    cudaMemsetAsync(bar, 0, NGRP * sizeof(unsigned));

    // fp16 weight copies for the GEMM chain
    wconv_k<<<64,   256>>>(Wi2,  Wi2h,  65536 / 4);
    wconv_k<<<64,   256>>>(Wi3,  Wi3h,  65536 / 4);
    wconv_k<<<1024, 256>>>(Wih0, Wih0h, 1048576 / 4);
    wconv_k<<<64,   256>>>(Wo1,  Wo1h,  65536 / 4);
    wconv_k<<<64,   256>>>(Wo2,  Wo2h,  65536 / 4);

    // Input MLP
    in_mlp1_k<<<TBc / 16, 256>>>(x, Wi1, bi1, hbuf0);
    dim3 gH(Hc / 128, TBc / 128);      // (2, 1024)
    gemm_h16_k<true, false, true, false><<<gH, 256, SMEM_GH>>>(hbuf0, Wi2h, bi2, nullptr, hbuf1, Hc);
    gemm_h16_k<true, false, true, false><<<gH, 256, SMEM_GH>>>(hbuf1, Wi3h, bi3, nullptr, hbuf0, Hc);

    // Layer-0 input projection for ALL timesteps (fp32 output + both biases)
    dim3 gG(H4c / 128, TBc / 128);     // (8, 1024)
    gemm_h16_k<false, false, false, true><<<gG, 256, SMEM_GH>>>(hbuf0, Wih0h, bih0, bhh0, G0, H4c);

    // Entire recurrence in one persistent launch
    lstm_persistent_k<<<NBLK, 256, SMEM_P>>>(Whh0, Wih1, Whh1, bih1, bhh1,
                                             G0, h0, hs);

    // Output MLP (PRE_RELU on hs)
    gemm_h16_k<true, true,  true, false><<<gH, 256, SMEM_GH>>>(hs,    Wo1h, bo1, nullptr, hbuf0, Hc);
    gemm_h16_k<true, false, true, false><<<gH, 256, SMEM_GH>>>(hbuf0, Wo2h, bo2, nullptr, hbuf1, Hc);
    out_mlp3_k<<<TBc / 8, 256>>>(hbuf1, Wo3, bo3, out);
}

// round 14
// speedup vs baseline: 1.3054x; 1.0057x over previous
#include <cuda_runtime.h>
#include <cuda_fp16.h>
#include <math.h>

// Problem constants
#define Tc   128
#define Bc   1024
#define LAGc 6
#define Hc   256
#define H4c  1024
#define TBc  (Tc * Bc)      // 131072
#define BHc  (Bc * Hc)      // 262144

// Persistent recurrence kernel geometry (fp16, K-chunk 16, 4-deep pipeline)
#define NGRP   8
#define NSUB   16
#define NBLK   (NGRP * NSUB)
#define W0STRH 264
#define W1STRH 520
#define AHSTR  24
#define ABUFH  (128 * AHSTR)
#define NABUF  4
#define SMEM_P ((64 * W0STRH + 64 * W1STRH + NABUF * ABUFH) * 2)   // 124928 bytes

// fp16 GEMM pipeline (round-11 proven)
#define HSTG   (128 * AHSTR)
#define GSTGH  (2 * HSTG)
#define SMEM_GH (3 * GSTGH * 2)       // 36864 bytes

// ---------------------------------------------------------------------------
__device__ __half g_hbuf0[TBc * Hc];
__device__ __half g_hbuf1[TBc * Hc];
__device__ float  g_G0[(size_t)TBc * H4c];
__device__ __half g_hs[TBc * Hc];           // h1 state (h1cur = hs[t])
__device__ __half g_h0[2 * BHc];            // layer-0 hidden ping-pong
__device__ __half g_wh[1310720];            // fp16 weights: Wi2|Wi3|Wih0|Wo1|Wo2
__device__ unsigned g_bar[NGRP];

// ---------------------------------------------------------------------------
__device__ __forceinline__ void mma16(float* d, const unsigned* a, const unsigned* b) {
    asm volatile("mma.sync.aligned.m16n8k16.row.col.f32.f16.f16.f32 "
        "{%0,%1,%2,%3}, {%4,%5,%6,%7}, {%8,%9}, {%0,%1,%2,%3};"
        : "+f"(d[0]), "+f"(d[1]), "+f"(d[2]), "+f"(d[3])
        : "r"(a[0]), "r"(a[1]), "r"(a[2]), "r"(a[3]), "r"(b[0]), "r"(b[1]));
}
__device__ __forceinline__ float sigmoidf_(float v) { return 1.f / (1.f + expf(-v)); }
__device__ __forceinline__ unsigned hrelu2(unsigned x) {
    __half2 h = __hmax2(*reinterpret_cast<__half2*>(&x), __float2half2_rn(0.f));
    return *reinterpret_cast<unsigned*>(&h);
}

__device__ __forceinline__ void cp_async16(void* dst, const void* src) {
    unsigned d = (unsigned)__cvta_generic_to_shared(dst);
    asm volatile("cp.async.ca.shared.global [%0], [%1], 16;\n" :: "r"(d), "l"(src));
}
__device__ __forceinline__ void cp_commit() {
    asm volatile("cp.async.commit_group;\n");
}
template<int N> __device__ __forceinline__ void cp_wait() {
    asm volatile("cp.async.wait_group %0;\n" :: "n"(N));
}
__device__ __forceinline__ void ldsm4h(unsigned* r, const __half* p) {
    unsigned a = (unsigned)__cvta_generic_to_shared(p);
    asm volatile("ldmatrix.sync.aligned.m8n8.x4.shared.b16 {%0,%1,%2,%3}, [%4];"
        : "=r"(r[0]), "=r"(r[1]), "=r"(r[2]), "=r"(r[3]) : "r"(a));
}

// Decoupled group barrier (recurrence)
__device__ __forceinline__ void bar_arrive(unsigned* ctr) {
    __syncthreads();
    if (threadIdx.x == 0)
        asm volatile("red.release.gpu.global.add.u32 [%0], 1;" :: "l"(ctr) : "memory");
}
__device__ __forceinline__ void bar_wait(unsigned* ctr, unsigned target) {
    if (threadIdx.x == 0) {
        unsigned v;
        do {
            asm volatile("ld.acquire.gpu.global.u32 %0, [%1];" : "=r"(v) : "l"(ctr) : "memory");
        } while (v < target);
    }
    __syncthreads();
}

// ---------------------------------------------------------------------------
// prep_k: ALL pre-work in ONE launch (keeps lstm_persistent_k at launch #6
// for the ncu -s 5 -c 1 capture window).
//   - fp32->fp16 weight conversion for Wi2|Wi3|Wih0|Wo1|Wo2
//   - zero h0 ping-pong buffers
//   - zero group barrier counters
// ---------------------------------------------------------------------------
__device__ __forceinline__ void conv4(const float* src, __half* dst, int i) {
    float4 v = ((const float4*)src)[i];
    ((__half2*)dst)[2 * i]     = __floats2half2_rn(v.x, v.y);
    ((__half2*)dst)[2 * i + 1] = __floats2half2_rn(v.z, v.w);
}
__global__ void __launch_bounds__(256) prep_k(
    const float* __restrict__ Wi2, const float* __restrict__ Wi3,
    const float* __restrict__ Wih0, const float* __restrict__ Wo1,
    const float* __restrict__ Wo2, __half* __restrict__ wh,
    __half* __restrict__ h0, unsigned* __restrict__ bar)
{
    int i = blockIdx.x * 256 + threadIdx.x;
    if (i < 16384)        conv4(Wi2,  wh,            i);
    else if (i < 32768)   conv4(Wi3,  wh + 65536,    i - 16384);
    else if (i < 294912)  conv4(Wih0, wh + 131072,   i - 32768);
    else if (i < 311296)  conv4(Wo1,  wh + 1179648,  i - 294912);
    else if (i < 327680)  conv4(Wo2,  wh + 1245184,  i - 311296);
    else if (i < 393216) {
        uint4 z = {0, 0, 0, 0};
        ((uint4*)h0)[i - 327680] = z;          // 65536 x 16B = 2*BHc halves
    } else if (i < 393216 + NGRP) {
        bar[i - 393216] = 0;
    }
}

// ---------------------------------------------------------------------------
// Kernel 1: u = half(relu(x @ Wi1^T + bi1))   [TB,6] -> [TB,256] fp16
// ---------------------------------------------------------------------------
__global__ void __launch_bounds__(256) in_mlp1_k(
    const float* __restrict__ x, const float* __restrict__ W,
    const float* __restrict__ b, __half* __restrict__ out)
{
    __shared__ float sW[Hc * LAGc];
    __shared__ float sb[Hc];
    __shared__ float sx[16 * LAGc];
    int tid = threadIdx.x;
    int m0  = blockIdx.x * 16;
    for (int i = tid; i < Hc * LAGc; i += 256) sW[i] = W[i];
    sb[tid] = b[tid];
    if (tid < 16 * LAGc) sx[tid] = x[m0 * LAGc + tid];
    __syncthreads();
    #pragma unroll
    for (int r = 0; r < 16; r++) {
        float acc = sb[tid];
        #pragma unroll
        for (int k = 0; k < LAGc; k++) acc += sx[r * LAGc + k] * sW[tid * LAGc + k];
        out[(m0 + r) * Hc + tid] = __float2half(fmaxf(acc, 0.f));
    }
}

// ---------------------------------------------------------------------------
// fp16 GEMM (round-11 proven): block 128x128, K=256, BK=16, 3-stage cp.async,
// ldmatrix, m16n8k16 HMMA fp32-accum. 8 warps (2m x 4n).
// ---------------------------------------------------------------------------
template<bool RELU_OUT, bool PRE_RELU, bool OUT_HALF, bool HAS_B2>
__global__ void __launch_bounds__(256, 2) gemm_h16_k(
    const __half* __restrict__ A, const __half* __restrict__ W,
    const float* __restrict__ b1, const float* __restrict__ b2,
    void* __restrict__ Cv, int N)
{
    extern __shared__ __half gsmh[];
    const int K = 256;
    int tid = threadIdx.x, lane = tid & 31, wid = tid >> 5;
    int wm = wid & 1, wn = wid >> 1;
    int m0 = blockIdx.y * 128, n0 = blockIdx.x * 128;
    int qr = lane >> 2, qk = lane & 3;
    int l8 = lane & 7, lsel = (lane >> 3) & 1, lhalf = lane >> 4;

    const __half* Ab = A + (size_t)m0 * K;
    const __half* Wb = W + (size_t)n0 * K;

    int srow = tid >> 1, sko = (tid & 1) * 8;

    int aoff[4], boff[2];
    #pragma unroll
    for (int mt = 0; mt < 4; mt++)
        aoff[mt] = (wm * 64 + mt * 16 + l8 + lsel * 8) * AHSTR + lhalf * 8;
    #pragma unroll
    for (int q = 0; q < 2; q++)
        boff[q] = HSTG + (wn * 32 + q * 16 + lhalf * 8 + l8) * AHSTR + lsel * 8;

    const int nk = K / 16;
    auto stage = [&](int kt) {
        __half* S = gsmh + (kt % 3) * GSTGH;
        cp_async16(S + srow * AHSTR + sko, Ab + (size_t)srow * K + kt * 16 + sko);
        cp_async16(S + HSTG + srow * AHSTR + sko, Wb + (size_t)srow * K + kt * 16 + sko);
        cp_commit();
    };

    stage(0);
    stage(1);

    float acc[4][4][4] = {};
    for (int kt = 0; kt < nk; kt++) {
        if (kt == nk - 1) cp_wait<0>(); else cp_wait<1>();
        __syncthreads();
        if (kt + 2 < nk) stage(kt + 2);
        const __half* S = gsmh + (kt % 3) * GSTGH;
        unsigned ua[4][4], ub[2][4];
        #pragma unroll
        for (int mt = 0; mt < 4; mt++) {
            ldsm4h(ua[mt], S + aoff[mt]);
            if (PRE_RELU) {
                #pragma unroll
                for (int i = 0; i < 4; i++) ua[mt][i] = hrelu2(ua[mt][i]);
            }
        }
        #pragma unroll
        for (int q = 0; q < 2; q++)
            ldsm4h(ub[q], S + boff[q]);
        #pragma unroll
        for (int mt = 0; mt < 4; mt++)
            #pragma unroll
            for (int q = 0; q < 2; q++) {
                mma16(acc[mt][2 * q],     ua[mt], ub[q]);
                mma16(acc[mt][2 * q + 1], ua[mt], ub[q] + 2);
            }
        __syncthreads();
    }

    #pragma unroll
    for (int nt = 0; nt < 4; nt++) {
        int col = n0 + wn * 32 + nt * 8 + 2 * qk;
        float bb0 = b1[col]     + (HAS_B2 ? b2[col]     : 0.f);
        float bb1 = b1[col + 1] + (HAS_B2 ? b2[col + 1] : 0.f);
        #pragma unroll
        for (int mt = 0; mt < 4; mt++) {
            int row = m0 + wm * 64 + mt * 16 + qr;
            float2 v0, v1;
            v0.x = acc[mt][nt][0] + bb0; v0.y = acc[mt][nt][1] + bb1;
            v1.x = acc[mt][nt][2] + bb0; v1.y = acc[mt][nt][3] + bb1;
            if (RELU_OUT) {
                v0.x=fmaxf(v0.x,0.f); v0.y=fmaxf(v0.y,0.f);
                v1.x=fmaxf(v1.x,0.f); v1.y=fmaxf(v1.y,0.f);
            }
            if (OUT_HALF) {
                __half* C = (__half*)Cv;
                *(__half2*)(C + (size_t)row * N + col)       = __floats2half2_rn(v0.x, v0.y);
                *(__half2*)(C + (size_t)(row + 8) * N + col) = __floats2half2_rn(v1.x, v1.y);
            } else {
                float* C = (float*)Cv;
                *(float2*)(C + (size_t)row * N + col)       = v0;
                *(float2*)(C + (size_t)(row + 8) * N + col) = v1;
            }
        }
    }
}

// ---------------------------------------------------------------------------
// Persistent LSTM helpers (fp16, chunk 16)
// ---------------------------------------------------------------------------
__device__ __forceinline__ void stage_warp_h(__half* Abuf, const __half* src_base,
                                             int wid, int lane) {
    int row = wid * 16 + (lane >> 1), kq = (lane & 1) * 8;
    cp_async16(Abuf + row * AHSTR + kq, src_base + (size_t)row * Hc + kq);
    cp_commit();
}

__device__ __forceinline__ void mma_chunk_h(
    const __half* Ab, int aoff, const __half* Wsm, int wstr, int woff, int kbase,
    float acc[8][4])
{
    unsigned a[4];
    ldsm4h(a, Ab + aoff);
    #pragma unroll
    for (int p = 0; p < 4; p++) {
        unsigned b[4];
        ldsm4h(b, Wsm + (size_t)(p * 16) * wstr + woff + kbase);
        mma16(acc[2 * p],     a, b);
        mma16(acc[2 * p + 1], a, b + 2);
    }
}

// ---------------------------------------------------------------------------
// Persistent recurrence: chunk 16, 4 A-buffers, lookahead 3; self-resets the
// barrier counters at exit so no pre-launch memset is needed.
// ---------------------------------------------------------------------------
__global__ void __launch_bounds__(256, 1) lstm_persistent_k(
    const float* __restrict__ Whh0, const float* __restrict__ Wih1,
    const float* __restrict__ Whh1, const float* __restrict__ bih1,
    const float* __restrict__ bhh1, const float* __restrict__ G0,
    __half* __restrict__ h0buf, __half* __restrict__ hs)
{
    extern __shared__ __half smh[];
    __half* W0   = smh;
    __half* W1   = smh + 64 * W0STRH;
    __half* Abuf = smh + 64 * W0STRH + 64 * W1STRH;

    int tid = threadIdx.x, lane = tid & 31, wid = tid >> 5;
    int qr = lane >> 2, qk = lane & 3;
    int grp = blockIdx.x >> 4, sub = blockIdx.x & 15;
    int m0  = grp * 128;
    int hc0 = sub * 16;

    for (int i = tid; i < 64 * 64; i += 256) {
        int n = i >> 6, kq = (i & 63) * 4;
        int gr = (n >> 4) * Hc + hc0 + (n & 15);
        float4 v = *(const float4*)(Whh0 + (size_t)gr * Hc + kq);
        __half2* dst = (__half2*)(W0 + n * W0STRH + kq);
        dst[0] = __floats2half2_rn(v.x, v.y);
        dst[1] = __floats2half2_rn(v.z, v.w);
    }
    for (int i = tid; i < 64 * 128; i += 256) {
        int n = i >> 7, kq = (i & 127) * 4;
        int gr = (n >> 4) * Hc + hc0 + (n & 15);
        const float* src = (kq < 256) ? (Wih1 + (size_t)gr * Hc + kq)
                                      : (Whh1 + (size_t)gr * Hc + (kq - 256));
        float4 v = *(const float4*)src;
        __half2* dst = (__half2*)(W1 + n * W1STRH + kq);
        dst[0] = __floats2half2_rn(v.x, v.y);
        dst[1] = __floats2half2_rn(v.z, v.w);
    }
    __syncthreads();

    int l8 = lane & 7, lsel = (lane >> 3) & 1, lhalf = lane >> 4;
    int aoff  = (wid * 16 + l8 + lsel * 8) * AHSTR + lhalf * 8;
    int woff0 = (lhalf * 8 + l8) * W0STRH + lsel * 8;
    int woff1 = (lhalf * 8 + l8) * W1STRH + lsel * 8;

    int wrow = wid * 16 + qr;
    float c0v[2][4] = {};
    float c1v[2][4] = {};
    float b1v[8][2];
    #pragma unroll
    for (int g = 0; g < 4; g++)
        #pragma unroll
        for (int h = 0; h < 2; h++)
            #pragma unroll
            for (int p = 0; p < 2; p++) {
                int n = g * Hc + hc0 + h * 8 + 2 * qk + p;
                b1v[g * 2 + h][p] = bih1[n] + bhh1[n];
            }

    unsigned* ctr = &g_bar[grp];

    for (int t = 0; t < Tc; t++) {
        const __half* h0prev = h0buf + (size_t)(t & 1) * BHc;
        __half*       h0cur  = h0buf + (size_t)((t + 1) & 1) * BHc;
        const __half* h1prev = hs + (size_t)(t - 1) * BHc;   // valid for t>0
        __half*       h1cur  = hs + (size_t)t * BHc;
        unsigned tB = (unsigned)(2 * t) * NSUB;
        unsigned tA = (unsigned)(2 * t + 1) * NSUB;

        // ================= layer 0 (K=256, 16 chunks) =================
        float2 gI[2][2], gF[2][2], gG[2][2], gO[2][2];
        {
            const float* g0r0 = G0 + ((size_t)t * Bc + m0 + wrow) * H4c + hc0;
            #pragma unroll
            for (int r = 0; r < 2; r++) {
                const float* g0r = g0r0 + (size_t)r * 8 * H4c;
                #pragma unroll
                for (int h = 0; h < 2; h++) {
                    int hcl = h * 8 + 2 * qk;
                    gI[r][h] = *(const float2*)(g0r + hcl);
                    gF[r][h] = *(const float2*)(g0r + 256 + hcl);
                    gG[r][h] = *(const float2*)(g0r + 512 + hcl);
                    gO[r][h] = *(const float2*)(g0r + 768 + hcl);
                }
            }
        }

        float acc[8][4] = {};
        {
            const __half* A0p = h0prev + (size_t)m0 * Hc;
            stage_warp_h(Abuf + 0 * ABUFH, A0p + 0 * 16, wid, lane);
            stage_warp_h(Abuf + 1 * ABUFH, A0p + 1 * 16, wid, lane);
            stage_warp_h(Abuf + 2 * ABUFH, A0p + 2 * 16, wid, lane);
            #pragma unroll 4
            for (int c = 0; c < 16; c++) {
                if (c < 13) {
                    stage_warp_h(Abuf + ((c + 3) & 3) * ABUFH, A0p + (c + 3) * 16, wid, lane);
                    cp_wait<3>();
                } else if (c == 13) cp_wait<2>();
                else if (c == 14) cp_wait<1>();
                else cp_wait<0>();
                __syncwarp();
                mma_chunk_h(Abuf + (c & 3) * ABUFH, aoff, W0, W0STRH, woff0, c * 16, acc);
            }
        }
        #pragma unroll
        for (int r = 0; r < 2; r++) {
            __half* hw = h0cur + (size_t)(m0 + wrow + r * 8) * Hc + hc0;
            #pragma unroll
            for (int h = 0; h < 2; h++) {
                int hcl = h * 8 + 2 * qk;
                float hv[2];
                #pragma unroll
                for (int p = 0; p < 2; p++) {
                    float gi = acc[0 + h][r * 2 + p] + (p ? gI[r][h].y : gI[r][h].x);
                    float gf = acc[2 + h][r * 2 + p] + (p ? gF[r][h].y : gF[r][h].x);
                    float gg = acc[4 + h][r * 2 + p] + (p ? gG[r][h].y : gG[r][h].x);
                    float go = acc[6 + h][r * 2 + p] + (p ? gO[r][h].y : gO[r][h].x);
                    float c  = c0v[r][h * 2 + p];
                    float c2 = sigmoidf_(gf) * c + sigmoidf_(gi) * tanhf(gg);
                    c0v[r][h * 2 + p] = c2;
                    hv[p] = sigmoidf_(go) * tanhf(c2);
                }
                *(__half2*)(hw + hcl) = __floats2half2_rn(hv[0], hv[1]);
            }
        }
        bar_arrive(ctr);                 // phase 2t+1

        // ================= layer 1 (K=512, 32 chunks; t=0 starts at 16) =====
        #pragma unroll
        for (int nf = 0; nf < 8; nf++)
            #pragma unroll
            for (int j = 0; j < 4; j++) acc[nf][j] = 0.f;

        {
            const __half* A0 = h0cur + (size_t)m0 * Hc;
            const __half* A1 = h1prev + (size_t)m0 * Hc;
            int cstart;
            if (t == 0) {
                cstart = 16;
                bar_wait(ctr, tA);
            } else {
                cstart = 0;
                bar_wait(ctr, tB);
            }
            auto srcof = [&](int cn) {
                return (cn < 16) ? (A1 + cn * 16) : (A0 + (cn - 16) * 16);
            };
            stage_warp_h(Abuf + 0 * ABUFH, srcof(cstart),     wid, lane);
            stage_warp_h(Abuf + 1 * ABUFH, srcof(cstart + 1), wid, lane);
            stage_warp_h(Abuf + 2 * ABUFH, srcof(cstart + 2), wid, lane);
            for (int c = cstart; c < 32; c++) {
                if (c < 29) {
                    if (c == 13) bar_wait(ctr, tA);
                    stage_warp_h(Abuf + ((c + 3 - cstart) & 3) * ABUFH, srcof(c + 3), wid, lane);
                    cp_wait<3>();
                } else if (c == 29) cp_wait<2>();
                else if (c == 30) cp_wait<1>();
                else cp_wait<0>();
                __syncwarp();
                int kb = (c < 16) ? (256 + c * 16) : ((c - 16) * 16);
                mma_chunk_h(Abuf + ((c - cstart) & 3) * ABUFH, aoff, W1, W1STRH, woff1, kb, acc);
            }
        }
        #pragma unroll
        for (int r = 0; r < 2; r++) {
            __half* hw = h1cur + (size_t)(m0 + wrow + r * 8) * Hc + hc0;
            #pragma unroll
            for (int h = 0; h < 2; h++) {
                int hcl = h * 8 + 2 * qk;
                float hv[2];
                #pragma unroll
                for (int p = 0; p < 2; p++) {
                    float gi = acc[0 + h][r * 2 + p] + b1v[0 + h][p];
                    float gf = acc[2 + h][r * 2 + p] + b1v[2 + h][p];
                    float gg = acc[4 + h][r * 2 + p] + b1v[4 + h][p];
                    float go = acc[6 + h][r * 2 + p] + b1v[6 + h][p];
                    float c  = c1v[r][h * 2 + p];
                    float c2 = sigmoidf_(gf) * c + sigmoidf_(gi) * tanhf(gg);
                    c1v[r][h * 2 + p] = c2;
                    hv[p] = sigmoidf_(go) * tanhf(c2);
                }
                *(__half2*)(hw + hcl) = __floats2half2_rn(hv[0], hv[1]);
            }
        }
        bar_arrive(ctr);                 // phase 2t+2
    }

    // Self-reset barrier counter for the next graph replay. All 2*Tc*NSUB
    // arrivals for this group have been issued; sub-0 waits for full count
    // (already satisfied or imminent) then clears it.
    if (sub == 0) {
        bar_wait(ctr, (unsigned)(2 * Tc) * NSUB);
        if (tid == 0)
            asm volatile("st.global.release.gpu.u32 [%0], 0;" :: "l"(ctr) : "memory");
    }
}

// ---------------------------------------------------------------------------
// Final layer: y = A @ Wo3^T + bo3  (N=6, K=256). A fp16, math fp32.
// ---------------------------------------------------------------------------
__global__ void __launch_bounds__(256) out_mlp3_k(
    const __half* __restrict__ A, const float* __restrict__ W,
    const float* __restrict__ b, float* __restrict__ out)
{
    __shared__ float sW[LAGc * Hc];
    __shared__ float sb[LAGc];
    int tid = threadIdx.x;
    for (int i = tid; i < LAGc * Hc; i += 256) sW[i] = W[i];
    if (tid < LAGc) sb[tid] = b[tid];
    __syncthreads();
    int w = tid >> 5, lane = tid & 31;
    int m = blockIdx.x * 8 + w;
    float a[8];
    #pragma unroll
    for (int j = 0; j < 8; j++) a[j] = __half2float(A[(size_t)m * Hc + lane + 32 * j]);
    #pragma unroll
    for (int n = 0; n < LAGc; n++) {
        float s = 0.f;
        #pragma unroll
        for (int j = 0; j < 8; j++) s += a[j] * sW[n * Hc + lane + 32 * j];
        #pragma unroll
        for (int o = 16; o > 0; o >>= 1) s += __shfl_xor_sync(0xffffffff, s, o);
        if (lane == n) out[m * LAGc + n] = s + sb[n];
    }
}

// ---------------------------------------------------------------------------
extern "C" void kernel_launch(void* const* d_in, const int* in_sizes, int n_in,
                              void* d_out, int out_size)
{
    const float* x    = (const float*)d_in[0];
    const float* Wi1  = (const float*)d_in[1];
    const float* bi1  = (const float*)d_in[2];
    const float* Wi2  = (const float*)d_in[3];
    const float* bi2  = (const float*)d_in[4];
    const float* Wi3  = (const float*)d_in[5];
    const float* bi3  = (const float*)d_in[6];
    const float* Wih0 = (const float*)d_in[7];
    const float* Whh0 = (const float*)d_in[8];
    const float* bih0 = (const float*)d_in[9];
    const float* bhh0 = (const float*)d_in[10];
    const float* Wih1 = (const float*)d_in[11];
    const float* Whh1 = (const float*)d_in[12];
    const float* bih1 = (const float*)d_in[13];
    const float* bhh1 = (const float*)d_in[14];
    const float* Wo1  = (const float*)d_in[15];
    const float* bo1  = (const float*)d_in[16];
    const float* Wo2  = (const float*)d_in[17];
    const float* bo2  = (const float*)d_in[18];
    const float* Wo3  = (const float*)d_in[19];
    const float* bo3  = (const float*)d_in[20];
    float* out = (float*)d_out;

    __half *hbuf0, *hbuf1, *hs, *h0, *wh;
    float *G0;
    unsigned* bar;
    cudaGetSymbolAddress((void**)&hbuf0, g_hbuf0);
    cudaGetSymbolAddress((void**)&hbuf1, g_hbuf1);
    cudaGetSymbolAddress((void**)&G0,    g_G0);
    cudaGetSymbolAddress((void**)&hs,    g_hs);
    cudaGetSymbolAddress((void**)&h0,    g_h0);
    cudaGetSymbolAddress((void**)&wh,    g_wh);
    cudaGetSymbolAddress((void**)&bar,   g_bar);

    __half* Wi2h  = wh;
    __half* Wi3h  = wh + 65536;
    __half* Wih0h = wh + 131072;
    __half* Wo1h  = wh + 1179648;
    __half* Wo2h  = wh + 1245184;

    cudaFuncSetAttribute(lstm_persistent_k,
                         cudaFuncAttributeMaxDynamicSharedMemorySize, SMEM_P);
    cudaFuncSetAttribute(gemm_h16_k<true,  false, true,  false>,
                         cudaFuncAttributeMaxDynamicSharedMemorySize, SMEM_GH);
    cudaFuncSetAttribute(gemm_h16_k<false, false, false, true >,
                         cudaFuncAttributeMaxDynamicSharedMemorySize, SMEM_GH);
    cudaFuncSetAttribute(gemm_h16_k<true,  true,  true,  false>,
                         cudaFuncAttributeMaxDynamicSharedMemorySize, SMEM_GH);

    // Launch #1: ALL prep (weights fp16, h0 zero, bar zero)
    prep_k<<<1537, 256>>>(Wi2, Wi3, Wih0, Wo1, Wo2, wh, h0, bar);

    // Launch #2: input MLP layer 1
    in_mlp1_k<<<TBc / 16, 256>>>(x, Wi1, bi1, hbuf0);

    // Launches #3, #4: input MLP layers 2-3
    dim3 gH(Hc / 128, TBc / 128);
    gemm_h16_k<true, false, true, false><<<gH, 256, SMEM_GH>>>(hbuf0, Wi2h, bi2, nullptr, hbuf1, Hc);
    gemm_h16_k<true, false, true, false><<<gH, 256, SMEM_GH>>>(hbuf1, Wi3h, bi3, nullptr, hbuf0, Hc);

    // Launch #5: layer-0 input projection for ALL timesteps
    dim3 gG(H4c / 128, TBc / 128);
    gemm_h16_k<false, false, false, true><<<gG, 256, SMEM_GH>>>(hbuf0, Wih0h, bih0, bhh0, G0, H4c);

    // Launch #6: persistent recurrence  (ncu -s 5 -c 1 captures THIS one)
    lstm_persistent_k<<<NBLK, 256, SMEM_P>>>(Whh0, Wih1, Whh1, bih1, bhh1,
                                             G0, h0, hs);

    // Output MLP
    gemm_h16_k<true, true,  true, false><<<gH, 256, SMEM_GH>>>(hs,    Wo1h, bo1, nullptr, hbuf0, Hc);
    gemm_h16_k<true, false, true, false><<<gH, 256, SMEM_GH>>>(hbuf0, Wo2h, bo2, nullptr, hbuf1, Hc);
    out_mlp3_k<<<TBc / 8, 256>>>(hbuf1, Wo3, bo3, out);
}

// round 15
// speedup vs baseline: 1.4963x; 1.1463x over previous
#include <cuda_runtime.h>
#include <cuda_fp16.h>
#include <math.h>

// Problem constants
#define Tc   128
#define Bc   1024
#define LAGc 6
#define Hc   256
#define H4c  1024
#define TBc  (Tc * Bc)      // 131072
#define BHc  (Bc * Hc)      // 262144

// Persistent recurrence kernel geometry (fp16, K-chunk 16, 4-deep pipeline)
#define NGRP   8
#define NSUB   16
#define NBLK   (NGRP * NSUB)
#define W0STRH 264
#define W1STRH 520
#define AHSTR  24
#define ABUFH  (128 * AHSTR)
#define NABUF  4
#define SMEM_P ((64 * W0STRH + 64 * W1STRH + NABUF * ABUFH) * 2)   // 124928 bytes

// fp16 GEMM pipeline: 4 stages x (A 128x16 + B 128x16), single sync per BK
#define HSTG   (128 * AHSTR)
#define GSTGH  (2 * HSTG)
#define SMEM_GH (4 * GSTGH * 2)       // 49152 bytes

// ---------------------------------------------------------------------------
__device__ __half g_hbuf0[TBc * Hc];
__device__ __half g_hbuf1[TBc * Hc];
__device__ float  g_G0[(size_t)TBc * H4c];
__device__ __half g_hs[TBc * Hc];           // h1 state (h1cur = hs[t])
__device__ __half g_h0[2 * BHc];            // layer-0 hidden ping-pong
__device__ __half g_wh[1310720];            // fp16 weights: Wi2|Wi3|Wih0|Wo1|Wo2
__device__ unsigned g_bar[NGRP];

// ---------------------------------------------------------------------------
__device__ __forceinline__ void mma16(float* d, const unsigned* a, const unsigned* b) {
    asm volatile("mma.sync.aligned.m16n8k16.row.col.f32.f16.f16.f32 "
        "{%0,%1,%2,%3}, {%4,%5,%6,%7}, {%8,%9}, {%0,%1,%2,%3};"
        : "+f"(d[0]), "+f"(d[1]), "+f"(d[2]), "+f"(d[3])
        : "r"(a[0]), "r"(a[1]), "r"(a[2]), "r"(a[3]), "r"(b[0]), "r"(b[1]));
}
// Fast MUFU-based activations. ex2/rcp approx rel err ~2^-22 — far below the
// fp16 h-storage quantization (2^-11), so network output shifts negligibly.
__device__ __forceinline__ float ex2f_(float x) {
    float y; asm("ex2.approx.f32 %0, %1;" : "=f"(y) : "f"(x)); return y;
}
__device__ __forceinline__ float rcpf_(float x) {
    float y; asm("rcp.approx.f32 %0, %1;" : "=f"(y) : "f"(x)); return y;
}
__device__ __forceinline__ float sigmoidf_(float v) {
    return rcpf_(1.f + ex2f_(-1.4426950408889634f * v));
}
__device__ __forceinline__ float tanhf_(float v) {
    // tanh(x) = 1 - 2/(e^{2x}+1); saturates correctly at +/-inf of ex2.
    return fmaf(-2.f, rcpf_(1.f + ex2f_(2.8853900817779268f * v)), 1.f);
}
__device__ __forceinline__ unsigned hrelu2(unsigned x) {
    __half2 h = __hmax2(*reinterpret_cast<__half2*>(&x), __float2half2_rn(0.f));
    return *reinterpret_cast<unsigned*>(&h);
}

__device__ __forceinline__ void cp_async16(void* dst, const void* src) {
    unsigned d = (unsigned)__cvta_generic_to_shared(dst);
    asm volatile("cp.async.ca.shared.global [%0], [%1], 16;\n" :: "r"(d), "l"(src));
}
__device__ __forceinline__ void cp_commit() {
    asm volatile("cp.async.commit_group;\n");
}
template<int N> __device__ __forceinline__ void cp_wait() {
    asm volatile("cp.async.wait_group %0;\n" :: "n"(N));
}
__device__ __forceinline__ void ldsm4h(unsigned* r, const __half* p) {
    unsigned a = (unsigned)__cvta_generic_to_shared(p);
    asm volatile("ldmatrix.sync.aligned.m8n8.x4.shared.b16 {%0,%1,%2,%3}, [%4];"
        : "=r"(r[0]), "=r"(r[1]), "=r"(r[2]), "=r"(r[3]) : "r"(a));
}

// Decoupled group barrier (recurrence)
__device__ __forceinline__ void bar_arrive(unsigned* ctr) {
    __syncthreads();
    if (threadIdx.x == 0)
        asm volatile("red.release.gpu.global.add.u32 [%0], 1;" :: "l"(ctr) : "memory");
}
__device__ __forceinline__ void bar_wait(unsigned* ctr, unsigned target) {
    if (threadIdx.x == 0) {
        unsigned v;
        do {
            asm volatile("ld.acquire.gpu.global.u32 %0, [%1];" : "=r"(v) : "l"(ctr) : "memory");
        } while (v < target);
    }
    __syncthreads();
}

// ---------------------------------------------------------------------------
// prep_k: ALL pre-work in ONE launch.
// ---------------------------------------------------------------------------
__device__ __forceinline__ void conv4(const float* src, __half* dst, int i) {
    float4 v = ((const float4*)src)[i];
    ((__half2*)dst)[2 * i]     = __floats2half2_rn(v.x, v.y);
    ((__half2*)dst)[2 * i + 1] = __floats2half2_rn(v.z, v.w);
}
__global__ void __launch_bounds__(256) prep_k(
    const float* __restrict__ Wi2, const float* __restrict__ Wi3,
    const float* __restrict__ Wih0, const float* __restrict__ Wo1,
    const float* __restrict__ Wo2, __half* __restrict__ wh,
    __half* __restrict__ h0, unsigned* __restrict__ bar)
{
    int i = blockIdx.x * 256 + threadIdx.x;
    if (i < 16384)        conv4(Wi2,  wh,            i);
    else if (i < 32768)   conv4(Wi3,  wh + 65536,    i - 16384);
    else if (i < 294912)  conv4(Wih0, wh + 131072,   i - 32768);
    else if (i < 311296)  conv4(Wo1,  wh + 1179648,  i - 294912);
    else if (i < 327680)  conv4(Wo2,  wh + 1245184,  i - 311296);
    else if (i < 393216) {
        uint4 z = {0, 0, 0, 0};
        ((uint4*)h0)[i - 327680] = z;
    } else if (i < 393216 + NGRP) {
        bar[i - 393216] = 0;
    }
}

// ---------------------------------------------------------------------------
// Kernel 1: u = half(relu(x @ Wi1^T + bi1))   [TB,6] -> [TB,256] fp16
// ---------------------------------------------------------------------------
__global__ void __launch_bounds__(256) in_mlp1_k(
    const float* __restrict__ x, const float* __restrict__ W,
    const float* __restrict__ b, __half* __restrict__ out)
{
    __shared__ float sW[Hc * LAGc];
    __shared__ float sb[Hc];
    __shared__ float sx[16 * LAGc];
    int tid = threadIdx.x;
    int m0  = blockIdx.x * 16;
    for (int i = tid; i < Hc * LAGc; i += 256) sW[i] = W[i];
    sb[tid] = b[tid];
    if (tid < 16 * LAGc) sx[tid] = x[m0 * LAGc + tid];
    __syncthreads();
    #pragma unroll
    for (int r = 0; r < 16; r++) {
        float acc = sb[tid];
        #pragma unroll
        for (int k = 0; k < LAGc; k++) acc += sx[r * LAGc + k] * sW[tid * LAGc + k];
        out[(m0 + r) * Hc + tid] = __float2half(fmaxf(acc, 0.f));
    }
}

// ---------------------------------------------------------------------------
// fp16 GEMM: block 128x128, K=256, BK=16, 4-stage cp.async with ONE
// __syncthreads per BK iteration (WAR-safe: stage kt+2 writes (kt+2)&3 which
// never collides with any buffer readable in the current lockstep iteration).
// ---------------------------------------------------------------------------
template<bool RELU_OUT, bool PRE_RELU, bool OUT_HALF, bool HAS_B2>
__global__ void __launch_bounds__(256, 2) gemm_h16_k(
    const __half* __restrict__ A, const __half* __restrict__ W,
    const float* __restrict__ b1, const float* __restrict__ b2,
    void* __restrict__ Cv, int N)
{
    extern __shared__ __half gsmh[];
    const int K = 256;
    int tid = threadIdx.x, lane = tid & 31, wid = tid >> 5;
    int wm = wid & 1, wn = wid >> 1;
    int m0 = blockIdx.y * 128, n0 = blockIdx.x * 128;
    int qr = lane >> 2, qk = lane & 3;
    int l8 = lane & 7, lsel = (lane >> 3) & 1, lhalf = lane >> 4;

    const __half* Ab = A + (size_t)m0 * K;
    const __half* Wb = W + (size_t)n0 * K;

    int srow = tid >> 1, sko = (tid & 1) * 8;

    int aoff[4], boff[2];
    #pragma unroll
    for (int mt = 0; mt < 4; mt++)
        aoff[mt] = (wm * 64 + mt * 16 + l8 + lsel * 8) * AHSTR + lhalf * 8;
    #pragma unroll
    for (int q = 0; q < 2; q++)
        boff[q] = HSTG + (wn * 32 + q * 16 + lhalf * 8 + l8) * AHSTR + lsel * 8;

    const int nk = K / 16;
    auto stage = [&](int kt) {
        __half* S = gsmh + (kt & 3) * GSTGH;
        cp_async16(S + srow * AHSTR + sko, Ab + (size_t)srow * K + kt * 16 + sko);
        cp_async16(S + HSTG + srow * AHSTR + sko, Wb + (size_t)srow * K + kt * 16 + sko);
        cp_commit();
    };

    stage(0);
    stage(1);

    float acc[4][4][4] = {};
    for (int kt = 0; kt < nk; kt++) {
        if (kt == nk - 1) cp_wait<0>(); else cp_wait<1>();
        __syncthreads();                       // single barrier per iteration
        if (kt + 2 < nk) stage(kt + 2);
        const __half* S = gsmh + (kt & 3) * GSTGH;
        unsigned ua[4][4], ub[2][4];
        #pragma unroll
        for (int mt = 0; mt < 4; mt++) {
            ldsm4h(ua[mt], S + aoff[mt]);
            if (PRE_RELU) {
                #pragma unroll
                for (int i = 0; i < 4; i++) ua[mt][i] = hrelu2(ua[mt][i]);
            }
        }
        #pragma unroll
        for (int q = 0; q < 2; q++)
            ldsm4h(ub[q], S + boff[q]);
        #pragma unroll
        for (int mt = 0; mt < 4; mt++)
            #pragma unroll
            for (int q = 0; q < 2; q++) {
                mma16(acc[mt][2 * q],     ua[mt], ub[q]);
                mma16(acc[mt][2 * q + 1], ua[mt], ub[q] + 2);
            }
    }

    #pragma unroll
    for (int nt = 0; nt < 4; nt++) {
        int col = n0 + wn * 32 + nt * 8 + 2 * qk;
        float bb0 = b1[col]     + (HAS_B2 ? b2[col]     : 0.f);
        float bb1 = b1[col + 1] + (HAS_B2 ? b2[col + 1] : 0.f);
        #pragma unroll
        for (int mt = 0; mt < 4; mt++) {
            int row = m0 + wm * 64 + mt * 16 + qr;
            float2 v0, v1;
            v0.x = acc[mt][nt][0] + bb0; v0.y = acc[mt][nt][1] + bb1;
            v1.x = acc[mt][nt][2] + bb0; v1.y = acc[mt][nt][3] + bb1;
            if (RELU_OUT) {
                v0.x=fmaxf(v0.x,0.f); v0.y=fmaxf(v0.y,0.f);
                v1.x=fmaxf(v1.x,0.f); v1.y=fmaxf(v1.y,0.f);
            }
            if (OUT_HALF) {
                __half* C = (__half*)Cv;
                *(__half2*)(C + (size_t)row * N + col)       = __floats2half2_rn(v0.x, v0.y);
                *(__half2*)(C + (size_t)(row + 8) * N + col) = __floats2half2_rn(v1.x, v1.y);
            } else {
                float* C = (float*)Cv;
                *(float2*)(C + (size_t)row * N + col)       = v0;
                *(float2*)(C + (size_t)(row + 8) * N + col) = v1;
            }
        }
    }
}

// ---------------------------------------------------------------------------
// Persistent LSTM helpers (fp16, chunk 16)
// ---------------------------------------------------------------------------
__device__ __forceinline__ void stage_warp_h(__half* Abuf, const __half* src_base,
                                             int wid, int lane) {
    int row = wid * 16 + (lane >> 1), kq = (lane & 1) * 8;
    cp_async16(Abuf + row * AHSTR + kq, src_base + (size_t)row * Hc + kq);
    cp_commit();
}

__device__ __forceinline__ void mma_chunk_h(
    const __half* Ab, int aoff, const __half* Wsm, int wstr, int woff, int kbase,
    float acc[8][4])
{
    unsigned a[4];
    ldsm4h(a, Ab + aoff);
    #pragma unroll
    for (int p = 0; p < 4; p++) {
        unsigned b[4];
        ldsm4h(b, Wsm + (size_t)(p * 16) * wstr + woff + kbase);
        mma16(acc[2 * p],     a, b);
        mma16(acc[2 * p + 1], a, b + 2);
    }
}

// ---------------------------------------------------------------------------
// Persistent recurrence: chunk 16, 4 A-buffers, lookahead 3; fast MUFU
// activations in the cell update; self-resets barrier counters at exit.
// ---------------------------------------------------------------------------
__global__ void __launch_bounds__(256, 1) lstm_persistent_k(
    const float* __restrict__ Whh0, const float* __restrict__ Wih1,
    const float* __restrict__ Whh1, const float* __restrict__ bih1,
    const float* __restrict__ bhh1, const float* __restrict__ G0,
    __half* __restrict__ h0buf, __half* __restrict__ hs)
{
    extern __shared__ __half smh[];
    __half* W0   = smh;
    __half* W1   = smh + 64 * W0STRH;
    __half* Abuf = smh + 64 * W0STRH + 64 * W1STRH;

    int tid = threadIdx.x, lane = tid & 31, wid = tid >> 5;
    int qr = lane >> 2, qk = lane & 3;
    int grp = blockIdx.x >> 4, sub = blockIdx.x & 15;
    int m0  = grp * 128;
    int hc0 = sub * 16;

    for (int i = tid; i < 64 * 64; i += 256) {
        int n = i >> 6, kq = (i & 63) * 4;
        int gr = (n >> 4) * Hc + hc0 + (n & 15);
        float4 v = *(const float4*)(Whh0 + (size_t)gr * Hc + kq);
        __half2* dst = (__half2*)(W0 + n * W0STRH + kq);
        dst[0] = __floats2half2_rn(v.x, v.y);
        dst[1] = __floats2half2_rn(v.z, v.w);
    }
    for (int i = tid; i < 64 * 128; i += 256) {
        int n = i >> 7, kq = (i & 127) * 4;
        int gr = (n >> 4) * Hc + hc0 + (n & 15);
        const float* src = (kq < 256) ? (Wih1 + (size_t)gr * Hc + kq)
                                      : (Whh1 + (size_t)gr * Hc + (kq - 256));
        float4 v = *(const float4*)src;
        __half2* dst = (__half2*)(W1 + n * W1STRH + kq);
        dst[0] = __floats2half2_rn(v.x, v.y);
        dst[1] = __floats2half2_rn(v.z, v.w);
    }
    __syncthreads();

    int l8 = lane & 7, lsel = (lane >> 3) & 1, lhalf = lane >> 4;
    int aoff  = (wid * 16 + l8 + lsel * 8) * AHSTR + lhalf * 8;
    int woff0 = (lhalf * 8 + l8) * W0STRH + lsel * 8;
    int woff1 = (lhalf * 8 + l8) * W1STRH + lsel * 8;

    int wrow = wid * 16 + qr;
    float c0v[2][4] = {};
    float c1v[2][4] = {};
    float b1v[8][2];
    #pragma unroll
    for (int g = 0; g < 4; g++)
        #pragma unroll
        for (int h = 0; h < 2; h++)
            #pragma unroll
            for (int p = 0; p < 2; p++) {
                int n = g * Hc + hc0 + h * 8 + 2 * qk + p;
                b1v[g * 2 + h][p] = bih1[n] + bhh1[n];
            }

    unsigned* ctr = &g_bar[grp];

    for (int t = 0; t < Tc; t++) {
        const __half* h0prev = h0buf + (size_t)(t & 1) * BHc;
        __half*       h0cur  = h0buf + (size_t)((t + 1) & 1) * BHc;
        const __half* h1prev = hs + (size_t)(t - 1) * BHc;   // valid for t>0
        __half*       h1cur  = hs + (size_t)t * BHc;
        unsigned tB = (unsigned)(2 * t) * NSUB;
        unsigned tA = (unsigned)(2 * t + 1) * NSUB;

        // ================= layer 0 (K=256, 16 chunks) =================
        float2 gI[2][2], gF[2][2], gG[2][2], gO[2][2];
        {
            const float* g0r0 = G0 + ((size_t)t * Bc + m0 + wrow) * H4c + hc0;
            #pragma unroll
            for (int r = 0; r < 2; r++) {
                const float* g0r = g0r0 + (size_t)r * 8 * H4c;
                #pragma unroll
                for (int h = 0; h < 2; h++) {
                    int hcl = h * 8 + 2 * qk;
                    gI[r][h] = *(const float2*)(g0r + hcl);
                    gF[r][h] = *(const float2*)(g0r + 256 + hcl);
                    gG[r][h] = *(const float2*)(g0r + 512 + hcl);
                    gO[r][h] = *(const float2*)(g0r + 768 + hcl);
                }
            }
        }

        float acc[8][4] = {};
        {
            const __half* A0p = h0prev + (size_t)m0 * Hc;
            stage_warp_h(Abuf + 0 * ABUFH, A0p + 0 * 16, wid, lane);
            stage_warp_h(Abuf + 1 * ABUFH, A0p + 1 * 16, wid, lane);
            stage_warp_h(Abuf + 2 * ABUFH, A0p + 2 * 16, wid, lane);
            #pragma unroll 4
            for (int c = 0; c < 16; c++) {
                if (c < 13) {
                    stage_warp_h(Abuf + ((c + 3) & 3) * ABUFH, A0p + (c + 3) * 16, wid, lane);
                    cp_wait<3>();
                } else if (c == 13) cp_wait<2>();
                else if (c == 14) cp_wait<1>();
                else cp_wait<0>();
                __syncwarp();
                mma_chunk_h(Abuf + (c & 3) * ABUFH, aoff, W0, W0STRH, woff0, c * 16, acc);
            }
        }
        #pragma unroll
        for (int r = 0; r < 2; r++) {
            __half* hw = h0cur + (size_t)(m0 + wrow + r * 8) * Hc + hc0;
            #pragma unroll
            for (int h = 0; h < 2; h++) {
                int hcl = h * 8 + 2 * qk;
                float hv[2];
                #pragma unroll
                for (int p = 0; p < 2; p++) {
                    float gi = acc[0 + h][r * 2 + p] + (p ? gI[r][h].y : gI[r][h].x);
                    float gf = acc[2 + h][r * 2 + p] + (p ? gF[r][h].y : gF[r][h].x);
                    float gg = acc[4 + h][r * 2 + p] + (p ? gG[r][h].y : gG[r][h].x);
                    float go = acc[6 + h][r * 2 + p] + (p ? gO[r][h].y : gO[r][h].x);
                    float c  = c0v[r][h * 2 + p];
                    float c2 = sigmoidf_(gf) * c + sigmoidf_(gi) * tanhf_(gg);
                    c0v[r][h * 2 + p] = c2;
                    hv[p] = sigmoidf_(go) * tanhf_(c2);
                }
                *(__half2*)(hw + hcl) = __floats2half2_rn(hv[0], hv[1]);
            }
        }
        bar_arrive(ctr);                 // phase 2t+1

        // ================= layer 1 (K=512, 32 chunks; t=0 starts at 16) =====
        #pragma unroll
        for (int nf = 0; nf < 8; nf++)
            #pragma unroll
            for (int j = 0; j < 4; j++) acc[nf][j] = 0.f;

        {
            const __half* A0 = h0cur + (size_t)m0 * Hc;
            const __half* A1 = h1prev + (size_t)m0 * Hc;
            int cstart;
            if (t == 0) {
                cstart = 16;
                bar_wait(ctr, tA);
            } else {
                cstart = 0;
                bar_wait(ctr, tB);
            }
            auto srcof = [&](int cn) {
                return (cn < 16) ? (A1 + cn * 16) : (A0 + (cn - 16) * 16);
            };
            stage_warp_h(Abuf + 0 * ABUFH, srcof(cstart),     wid, lane);
            stage_warp_h(Abuf + 1 * ABUFH, srcof(cstart + 1), wid, lane);
            stage_warp_h(Abuf + 2 * ABUFH, srcof(cstart + 2), wid, lane);
            for (int c = cstart; c < 32; c++) {
                if (c < 29) {
                    if (c == 13) bar_wait(ctr, tA);
                    stage_warp_h(Abuf + ((c + 3 - cstart) & 3) * ABUFH, srcof(c + 3), wid, lane);
                    cp_wait<3>();
                } else if (c == 29) cp_wait<2>();
                else if (c == 30) cp_wait<1>();
                else cp_wait<0>();
                __syncwarp();
                int kb = (c < 16) ? (256 + c * 16) : ((c - 16) * 16);
                mma_chunk_h(Abuf + ((c - cstart) & 3) * ABUFH, aoff, W1, W1STRH, woff1, kb, acc);
            }
        }
        #pragma unroll
        for (int r = 0; r < 2; r++) {
            __half* hw = h1cur + (size_t)(m0 + wrow + r * 8) * Hc + hc0;
            #pragma unroll
            for (int h = 0; h < 2; h++) {
                int hcl = h * 8 + 2 * qk;
                float hv[2];
                #pragma unroll
                for (int p = 0; p < 2; p++) {
                    float gi = acc[0 + h][r * 2 + p] + b1v[0 + h][p];
                    float gf = acc[2 + h][r * 2 + p] + b1v[2 + h][p];
                    float gg = acc[4 + h][r * 2 + p] + b1v[4 + h][p];
                    float go = acc[6 + h][r * 2 + p] + b1v[6 + h][p];
                    float c  = c1v[r][h * 2 + p];
                    float c2 = sigmoidf_(gf) * c + sigmoidf_(gi) * tanhf_(gg);
                    c1v[r][h * 2 + p] = c2;
                    hv[p] = sigmoidf_(go) * tanhf_(c2);
                }
                *(__half2*)(hw + hcl) = __floats2half2_rn(hv[0], hv[1]);
            }
        }
        bar_arrive(ctr);                 // phase 2t+2
    }

    // Self-reset barrier counter for the next graph replay.
    if (sub == 0) {
        bar_wait(ctr, (unsigned)(2 * Tc) * NSUB);
        if (tid == 0)
            asm volatile("st.global.release.gpu.u32 [%0], 0;" :: "l"(ctr) : "memory");
    }
}

// ---------------------------------------------------------------------------
// Final layer: y = A @ Wo3^T + bo3  (N=6, K=256). A fp16, math fp32.
// ---------------------------------------------------------------------------
__global__ void __launch_bounds__(256) out_mlp3_k(
    const __half* __restrict__ A, const float* __restrict__ W,
    const float* __restrict__ b, float* __restrict__ out)
{
    __shared__ float sW[LAGc * Hc];
    __shared__ float sb[LAGc];
    int tid = threadIdx.x;
    for (int i = tid; i < LAGc * Hc; i += 256) sW[i] = W[i];
    if (tid < LAGc) sb[tid] = b[tid];
    __syncthreads();
    int w = tid >> 5, lane = tid & 31;
    int m = blockIdx.x * 8 + w;
    float a[8];
    #pragma unroll
    for (int j = 0; j < 8; j++) a[j] = __half2float(A[(size_t)m * Hc + lane + 32 * j]);
    #pragma unroll
    for (int n = 0; n < LAGc; n++) {
        float s = 0.f;
        #pragma unroll
        for (int j = 0; j < 8; j++) s += a[j] * sW[n * Hc + lane + 32 * j];
        #pragma unroll
        for (int o = 16; o > 0; o >>= 1) s += __shfl_xor_sync(0xffffffff, s, o);
        if (lane == n) out[m * LAGc + n] = s + sb[n];
    }
}

// ---------------------------------------------------------------------------
extern "C" void kernel_launch(void* const* d_in, const int* in_sizes, int n_in,
                              void* d_out, int out_size)
{
    const float* x    = (const float*)d_in[0];
    const float* Wi1  = (const float*)d_in[1];
    const float* bi1  = (const float*)d_in[2];
    const float* Wi2  = (const float*)d_in[3];
    const float* bi2  = (const float*)d_in[4];
    const float* Wi3  = (const float*)d_in[5];
    const float* bi3  = (const float*)d_in[6];
    const float* Wih0 = (const float*)d_in[7];
    const float* Whh0 = (const float*)d_in[8];
    const float* bih0 = (const float*)d_in[9];
    const float* bhh0 = (const float*)d_in[10];
    const float* Wih1 = (const float*)d_in[11];
    const float* Whh1 = (const float*)d_in[12];
    const float* bih1 = (const float*)d_in[13];
    const float* bhh1 = (const float*)d_in[14];
    const float* Wo1  = (const float*)d_in[15];
    const float* bo1  = (const float*)d_in[16];
    const float* Wo2  = (const float*)d_in[17];
    const float* bo2  = (const float*)d_in[18];
    const float* Wo3  = (const float*)d_in[19];
    const float* bo3  = (const float*)d_in[20];
    float* out = (float*)d_out;

    __half *hbuf0, *hbuf1, *hs, *h0, *wh;
    float *G0;
    unsigned* bar;
    cudaGetSymbolAddress((void**)&hbuf0, g_hbuf0);
    cudaGetSymbolAddress((void**)&hbuf1, g_hbuf1);
    cudaGetSymbolAddress((void**)&G0,    g_G0);
    cudaGetSymbolAddress((void**)&hs,    g_hs);
    cudaGetSymbolAddress((void**)&h0,    g_h0);
    cudaGetSymbolAddress((void**)&wh,    g_wh);
    cudaGetSymbolAddress((void**)&bar,   g_bar);

    __half* Wi2h  = wh;
    __half* Wi3h  = wh + 65536;
    __half* Wih0h = wh + 131072;
    __half* Wo1h  = wh + 1179648;
    __half* Wo2h  = wh + 1245184;

    cudaFuncSetAttribute(lstm_persistent_k,
                         cudaFuncAttributeMaxDynamicSharedMemorySize, SMEM_P);
    cudaFuncSetAttribute(gemm_h16_k<true,  false, true,  false>,
                         cudaFuncAttributeMaxDynamicSharedMemorySize, SMEM_GH);
    cudaFuncSetAttribute(gemm_h16_k<false, false, false, true >,
                         cudaFuncAttributeMaxDynamicSharedMemorySize, SMEM_GH);
    cudaFuncSetAttribute(gemm_h16_k<true,  true,  true,  false>,
                         cudaFuncAttributeMaxDynamicSharedMemorySize, SMEM_GH);

    // Launch #1: ALL prep (weights fp16, h0 zero, bar zero)
    prep_k<<<1537, 256>>>(Wi2, Wi3, Wih0, Wo1, Wo2, wh, h0, bar);

    // Launch #2: input MLP layer 1
    in_mlp1_k<<<TBc / 16, 256>>>(x, Wi1, bi1, hbuf0);

    // Launches #3, #4: input MLP layers 2-3
    dim3 gH(Hc / 128, TBc / 128);
    gemm_h16_k<true, false, true, false><<<gH, 256, SMEM_GH>>>(hbuf0, Wi2h, bi2, nullptr, hbuf1, Hc);
    gemm_h16_k<true, false, true, false><<<gH, 256, SMEM_GH>>>(hbuf1, Wi3h, bi3, nullptr, hbuf0, Hc);

    // Launch #5: layer-0 input projection for ALL timesteps
    dim3 gG(H4c / 128, TBc / 128);
    gemm_h16_k<false, false, false, true><<<gG, 256, SMEM_GH>>>(hbuf0, Wih0h, bih0, bhh0, G0, H4c);

    // Launch #6: persistent recurrence
    lstm_persistent_k<<<NBLK, 256, SMEM_P>>>(Whh0, Wih1, Whh1, bih1, bhh1,
                                             G0, h0, hs);

    // Output MLP
    gemm_h16_k<true, true,  true, false><<<gH, 256, SMEM_GH>>>(hs,    Wo1h, bo1, nullptr, hbuf0, Hc);
    gemm_h16_k<true, false, true, false><<<gH, 256, SMEM_GH>>>(hbuf0, Wo2h, bo2, nullptr, hbuf1, Hc);
    out_mlp3_k<<<TBc / 8, 256>>>(hbuf1, Wo3, bo3, out);
}